// round 9
// baseline (speedup 1.0000x reference)
#include <cuda_runtime.h>
#include <math.h>

#define B_ 32
#define L_ 4096
#define N_ 256
#define NF 2048          // packed complex FFT size (L/2)
#define FBINS 2049       // rfft bins
#define NT 256
#define NSERIES (B_*N_)

__device__ float  g_xt[(size_t)B_*N_*L_];   // (B,N,L) transposed input
__device__ float2 g_tw[NF/2];               // exp(-2*pi*i*j/2048)
__device__ float2 g_rot[NF];                // exp(-pi*i*k/2048)

// XOR swizzle on float2 indices: conflict-free smem FFT exchanges
#define FZ(a) ((a) ^ (((a) >> 3) & 0xF))
// padded natural-order spectrum index (writes provably conflict-free)
#define YA(k) ((k) + ((k) >> 3))

__device__ __forceinline__ float2 cmul(float2 a, float2 b) {
    return make_float2(a.x*b.x - a.y*b.y, a.x*b.y + a.y*b.x);
}
__device__ __forceinline__ float2 cadd(float2 a, float2 b) { return make_float2(a.x+b.x, a.y+b.y); }
__device__ __forceinline__ float2 csub(float2 a, float2 b) { return make_float2(a.x-b.x, a.y-b.y); }
__device__ __forceinline__ float2 cnegi(float2 a) { return make_float2(a.y, -a.x); }  // a * (-i)

// ---------------------------------------------------------------------------
// Tiled transpose x (B,L,N) -> g_xt (B,N,L); block (0,0,0) also fills twiddle tables.
__global__ void transpose_kernel(const float* __restrict__ x) {
    __shared__ float tile[32][33];
    int b  = blockIdx.z;
    int l0 = blockIdx.x << 5;
    int n0 = blockIdx.y << 5;
    int tx = threadIdx.x, ty = threadIdx.y;   // (32, 8)
    if (blockIdx.x == 0 && blockIdx.y == 0 && blockIdx.z == 0) {
        int tid = ty * 32 + tx;
        for (int i = tid; i < NF/2; i += 256) {
            float ang = -6.2831853071795864769f * (float)i / (float)NF;
            float sn, cs; sincosf(ang, &sn, &cs);
            g_tw[i] = make_float2(cs, sn);
        }
        for (int i = tid; i < NF; i += 256) {
            float ang = -3.1415926535897932385f * (float)i / (float)NF;
            float sn, cs; sincosf(ang, &sn, &cs);
            g_rot[i] = make_float2(cs, sn);
        }
    }
    #pragma unroll
    for (int i = 0; i < 32; i += 8)
        tile[ty + i][tx] = x[((size_t)b * L_ + (l0 + ty + i)) * N_ + n0 + tx];
    __syncthreads();
    #pragma unroll
    for (int i = 0; i < 32; i += 8)
        g_xt[((size_t)b * N_ + (n0 + ty + i)) * L_ + l0 + tx] = tile[tx][ty + i];
}

// ---------------------------------------------------------------------------
// radix-4 DIF butterfly (in-place digit placement)
__device__ __forceinline__ void bfy4(float2* x, float2 wa, float2 wb) {
    float2 wami = cnegi(wa);
    float2 t0 = cadd(x[0], x[2]), u0 = cmul(csub(x[0], x[2]), wa);
    float2 t1 = cadd(x[1], x[3]), u1 = cmul(csub(x[1], x[3]), wami);
    x[0] = cadd(t0, t1); x[1] = cmul(csub(t0, t1), wb);
    x[2] = cadd(u0, u1); x[3] = cmul(csub(u0, u1), wb);
}

// radix-8 DIF butterfly = 3 in-place radix-2 stages on 8 register values.
__device__ __forceinline__ void bfy8(float2* x, float2 wa, float2 wb, float2 wc) {
    const float R2 = 0.70710678118654752440f;
    float2 wa1 = cmul(wa, make_float2(R2, -R2));
    float2 wa2 = cnegi(wa);
    float2 wa3 = cnegi(wa1);
    float2 wbi = cnegi(wb);
    float2 d;
    d = csub(x[0], x[4]); x[0] = cadd(x[0], x[4]); x[4] = cmul(d, wa);
    d = csub(x[1], x[5]); x[1] = cadd(x[1], x[5]); x[5] = cmul(d, wa1);
    d = csub(x[2], x[6]); x[2] = cadd(x[2], x[6]); x[6] = cmul(d, wa2);
    d = csub(x[3], x[7]); x[3] = cadd(x[3], x[7]); x[7] = cmul(d, wa3);
    d = csub(x[0], x[2]); x[0] = cadd(x[0], x[2]); x[2] = cmul(d, wb);
    d = csub(x[1], x[3]); x[1] = cadd(x[1], x[3]); x[3] = cmul(d, wbi);
    d = csub(x[4], x[6]); x[4] = cadd(x[4], x[6]); x[6] = cmul(d, wb);
    d = csub(x[5], x[7]); x[5] = cadd(x[5], x[7]); x[7] = cmul(d, wbi);
    d = csub(x[0], x[1]); x[0] = cadd(x[0], x[1]); x[1] = cmul(d, wc);
    d = csub(x[2], x[3]); x[2] = cadd(x[2], x[3]); x[3] = cmul(d, wc);
    d = csub(x[4], x[5]); x[4] = cadd(x[4], x[5]); x[5] = cmul(d, wc);
    d = csub(x[6], x[7]); x[6] = cadd(x[6], x[7]); x[7] = cmul(d, wc);
}

// ---------------------------------------------------------------------------
// One CTA per (b,n) series.
__global__ __launch_bounds__(NT, 5) void feat_kernel(
    const float* __restrict__ w1, const float* __restrict__ b1v,
    const float* __restrict__ w2, const float* __restrict__ b2v,
    float* __restrict__ out)
{
    __shared__ float s[4608];    // [0,4128): series+pad / FFT z[]; later per-thread lists
    __shared__ float yr[2304];   // natural-order spectrum real (YA padding)
    __shared__ float yi[2304];   // natural-order spectrum imag (YA padding)
    __shared__ float red[304];
    // red layout: [0..71] 9x8 moment partials | [72..79] ampsum | [80..87] ampmax
    //             [88..159] warp-list vals | [160..231] warp-list keys
    //             [232..255] head24 | [256..279] tail24 | [280..297] global top9

    const int tid  = threadIdx.x;
    const int lane = tid & 31, warp = tid >> 5;

    // ---- phase 1: pure load + STS (no register retention) ----
    {
        const float4* __restrict__ src4 =
            (const float4*)(g_xt + (size_t)blockIdx.x * L_ + tid * 16);
        float4* sm4 = (float4*)s;
        #pragma unroll
        for (int c = 0; c < 4; ++c) sm4[tid*4 + c] = src4[c];
    }
    if (tid < 8) ((float4*)s)[1024 + tid] = make_float4(0.f, 0.f, 0.f, 0.f); // zero pad
    __syncthreads();   // sync 1: series + pad complete in smem

    // edge stashes for autocorr boundary terms (from smem)
    if (tid == 0)   { for (int k = 0; k < 24; k++) red[232 + k] = s[k]; }
    if (tid == 255) { for (int k = 0; k < 24; k++) red[256 + k] = s[4072 + k]; }

    // ---- moments + autocorr: 28-float sliding window over [base, base+40) ----
    {
        const int base = tid * 16;
        float w[28];
        #pragma unroll
        for (int c = 0; c < 7; ++c) {
            float4 v = *(const float4*)(s + base + 4*c);
            w[4*c+0] = v.x; w[4*c+1] = v.y; w[4*c+2] = v.z; w[4*c+3] = v.w;
        }
        float acc[9];   // s1 s2 s3 s4 R1 R3 R6 R12 R24 (raw sums)
        #pragma unroll
        for (int q = 0; q < 9; q++) acc[q] = 0.f;
        #pragma unroll
        for (int b = 0; b < 4; ++b) {
            #pragma unroll
            for (int t = 0; t < 4; ++t) {
                float v = w[t], v2 = v*v;
                acc[0] += v; acc[1] += v2; acc[2] += v2*v; acc[3] += v2*v2;
                acc[4] += v * w[t+1];
                acc[5] += v * w[t+3];
                acc[6] += v * w[t+6];
                acc[7] += v * w[t+12];
                acc[8] += v * w[t+24];
            }
            if (b < 3) {
                #pragma unroll
                for (int j = 0; j < 24; j++) w[j] = w[j+4];
                float4 v = *(const float4*)(s + base + 28 + 4*b);
                w[24] = v.x; w[25] = v.y; w[26] = v.z; w[27] = v.w;
            }
        }
        // warp-reduce 9 raw sums -> red partials (finalized by tid0 at the end)
        #pragma unroll
        for (int q = 0; q < 9; q++) {
            float v = acc[q];
            #pragma unroll
            for (int o = 16; o > 0; o >>= 1) v += __shfl_down_sync(~0u, v, o);
            if (lane == 0) red[q*8 + warp] = v;
        }
    }

    // ---- FFT group 0: radix-4 (S=2048), natural read -> swizzled write ----
    float2* z = (float2*)s;
    float2 xa[4], xb[4];
    #pragma unroll
    for (int j = 0; j < 4; j++) { xa[j] = z[tid + 512*j]; xb[j] = z[tid + 256 + 512*j]; }
    bfy4(xa, g_tw[tid],       g_tw[2*tid]);
    bfy4(xb, g_tw[tid + 256], g_tw[2*tid + 512]);
    __syncthreads();   // sync 2
    #pragma unroll
    for (int j = 0; j < 4; j++) {
        z[FZ(tid + 512*j)]       = xa[j];
        z[FZ(tid + 256 + 512*j)] = xb[j];
    }
    __syncthreads();   // sync 3

    float2 zx[8];
    // ---- group 1: radix-8, S=512, q=64 ----
    {
        int o = tid & 63, base = (tid >> 6) * 512 + o;
        #pragma unroll
        for (int j = 0; j < 8; j++) zx[j] = z[FZ(base + 64*j)];
        bfy8(zx, g_tw[4*o], g_tw[8*o], g_tw[16*o]);
        #pragma unroll
        for (int j = 0; j < 8; j++) z[FZ(base + 64*j)] = zx[j];
    }
    __syncthreads();   // sync 4
    // ---- group 2: radix-8, S=64, q=8 ----
    {
        int o = tid & 7, base = (tid >> 3) * 64 + o;
        #pragma unroll
        for (int j = 0; j < 8; j++) zx[j] = z[FZ(base + 8*j)];
        bfy8(zx, g_tw[32*o], g_tw[64*o], g_tw[128*o]);
        #pragma unroll
        for (int j = 0; j < 8; j++) z[FZ(base + 8*j)] = zx[j];
    }
    __syncthreads();   // sync 5
    // ---- group 3: radix-8, S=8, q=1 (unit twiddles), fused de-reversal ----
    {
        int base = tid * 8;
        const float2 one = make_float2(1.f, 0.f);
        #pragma unroll
        for (int j = 0; j < 8; j++) zx[j] = z[FZ(base + j)];
        bfy8(zx, one, one, one);
        #pragma unroll
        for (int j = 0; j < 8; j++) {
            int k = __brev((unsigned)(base + j)) >> 21;   // natural bin
            int a = YA(k);
            yr[a] = zx[j].x; yi[a] = zx[j].y;
        }
    }
    __syncthreads();   // sync 6: yr/yi ready; all z reads done (s reusable)

    // ---- unpack amplitudes via conjugate-pair symmetry + local sort ----
    float av[9]; int ak[9];
    float Ssum = 0.f, Smax = 0.f;
    #pragma unroll
    for (int c = 0; c < 4; ++c) {
        int k = 1 + tid + 256*c;          // 1..1024
        int m = 2048 - k;                 // 1024..2047
        int ka = YA(k), ma = YA(m);
        float zkr = yr[ka], zki = yi[ka];
        float zmr = yr[ma], zmi = yi[ma];
        float er  = 0.5f * (zkr + zmr);
        float ei  = 0.5f * (zki - zmi);
        float orr = 0.5f * (zki + zmi);
        float oi  = -0.5f * (zkr - zmr);
        float2 w = g_rot[k];
        float pr = w.x*orr - w.y*oi;
        float pi = w.x*oi  + w.y*orr;
        float xr = er + pr, xi2 = ei + pi;
        float ampk = sqrtf(xr*xr + xi2*xi2);
        float qr = er - pr, qi = ei - pi;
        float ampm = sqrtf(qr*qr + qi*qi);
        av[c] = ampk; ak[c] = k;
        Ssum += ampk; Smax = fmaxf(Smax, ampk);
        if (k == 1024) { av[4+c] = -1.f; ak[4+c] = 0x3fffffff; }  // self-pair dup
        else {
            av[4+c] = ampm; ak[4+c] = m;
            Ssum += ampm; Smax = fmaxf(Smax, ampm);
        }
    }
    av[8] = -1.f; ak[8] = 0x3fffffff;

    float a0 = 0.f, aN = 0.f;
    if (tid == 0) {
        float z0r = yr[0], z0i = yi[0];   // YA(0)==0
        a0 = fabsf(z0r + z0i);            // bin 0
        aN = fabsf(z0r - z0i);            // bin 2048
        Ssum += a0 + aN;
        Smax = fmaxf(Smax, fmaxf(a0, aN));
    }

    // sort av[0..7] desc (tie -> lower index), Batcher 19 CE
    #define CE(i,j) { if (av[i] < av[j] || (av[i]==av[j] && ak[i] > ak[j])) { \
        float tv=av[i]; av[i]=av[j]; av[j]=tv; int tk=ak[i]; ak[i]=ak[j]; ak[j]=tk; } }
    CE(0,1) CE(2,3) CE(4,5) CE(6,7)
    CE(0,2) CE(1,3) CE(4,6) CE(5,7)
    CE(1,2) CE(5,6)
    CE(0,4) CE(1,5) CE(2,6) CE(3,7)
    CE(2,4) CE(3,5)
    CE(1,2) CE(3,4) CE(5,6)
    // tid0: insert bins 0 and 2048 (insert-with-drop keeps thread top-9)
    if (tid == 0) {
        if (a0 > av[8] || (a0 == av[8] && 0 < ak[8])) { av[8] = a0; ak[8] = 0; }
        CE(7,8) CE(6,7) CE(5,6) CE(4,5) CE(3,4) CE(2,3) CE(1,2) CE(0,1)
        if (aN > av[8] || (aN == av[8] && 2048 < ak[8])) { av[8] = aN; ak[8] = 2048; }
        CE(7,8) CE(6,7) CE(5,6) CE(4,5) CE(3,4) CE(2,3) CE(1,2) CE(0,1)
    } else {
        CE(7,8) CE(6,7) CE(5,6) CE(4,5) CE(3,4) CE(2,3) CE(1,2) CE(0,1)
    }
    #undef CE

    // amp sum/max warp partials
    {
        float sv = Ssum, mv = Smax;
        #pragma unroll
        for (int o = 16; o > 0; o >>= 1) {
            sv += __shfl_down_sync(~0u, sv, o);
            mv = fmaxf(mv, __shfl_down_sync(~0u, mv, o));
        }
        if (lane == 0) { red[72 + warp] = sv; red[80 + warp] = mv; }
    }

    // spill per-thread sorted lists into s (s dead since sync 6; each thread
    // writes + later reads only its own slots — no barrier needed for Phase A)
    #pragma unroll
    for (int r = 0; r < 9; ++r) {
        s[tid*9 + r]        = av[r];
        s[2304 + tid*9 + r] = __int_as_float(ak[r]);
    }

    // ---- Phase A: warp-local tournament -> warp top-9 (reads own list only) ----
    {
        int p = 0;
        #pragma unroll
        for (int r = 0; r < 9; ++r) {
            float hv = (p < 9) ? s[tid*9 + p] : -2.f;
            int   hk = (p < 9) ? __float_as_int(s[2304 + tid*9 + p]) : 0x7fffffff;
            float bv = hv; int bk = hk;
            #pragma unroll
            for (int o = 16; o > 0; o >>= 1) {
                float ov = __shfl_down_sync(~0u, bv, o);
                int   ok = __shfl_down_sync(~0u, bk, o);
                if (ov > bv || (ov == bv && ok < bk)) { bv = ov; bk = ok; }
            }
            int wk = __shfl_sync(~0u, bk, 0);
            if (hk == wk) p++;
            if (lane == 0) {
                red[88  + warp*9 + r] = bv;
                red[160 + warp*9 + r] = __int_as_float(bk);
            }
        }
    }
    __syncthreads();   // sync 7: warp winners + amp partials visible

    // ---- Phase B: warp 0 merges 8 warp lists -> global top-9 ----
    if (warp == 0) {
        int p = 0;
        #pragma unroll
        for (int r = 0; r < 9; ++r) {
            float hv = (lane < 8 && p < 9) ? red[88 + lane*9 + p] : -2.f;
            int   hk = (lane < 8 && p < 9) ? __float_as_int(red[160 + lane*9 + p]) : 0x7fffffff;
            float bv = hv; int bk = hk;
            #pragma unroll
            for (int o = 4; o > 0; o >>= 1) {
                float ov = __shfl_down_sync(~0u, bv, o);
                int   ok = __shfl_down_sync(~0u, bk, o);
                if (ov > bv || (ov == bv && ok < bk)) { bv = ov; bk = ok; }
            }
            int wk = __shfl_sync(~0u, bk, 0);
            if (hk == wk) p++;
            if (lane == 0) {
                red[280 + r] = bv;
                red[289 + r] = __int_as_float(bk);
            }
        }
    }

    // ---- epilogue (thread 0, same warp as Phase B writes) ----
    if (tid == 0) {
        const int lags[5] = {1, 3, 6, 12, 24};
        float s1 = 0.f, s2 = 0.f, s3 = 0.f, s4 = 0.f, R[5] = {0,0,0,0,0};
        float S = 0.f, maxamp = 0.f;
        #pragma unroll
        for (int i = 0; i < 8; i++) {
            s1 += red[0*8+i]; s2 += red[1*8+i]; s3 += red[2*8+i]; s4 += red[3*8+i];
            R[0] += red[4*8+i]; R[1] += red[5*8+i]; R[2] += red[6*8+i];
            R[3] += red[7*8+i]; R[4] += red[8*8+i];
            S += red[72+i]; maxamp = fmaxf(maxamp, red[80+i]);
        }
        float topv[9]; int topi[9];
        #pragma unroll
        for (int r = 0; r < 9; ++r) {
            topv[r] = red[280 + r];
            topi[r] = __float_as_int(red[289 + r]);
        }
        // edge prefix/suffix sums
        float H[25], T[25];
        H[0] = 0.f; T[0] = 0.f;
        #pragma unroll
        for (int k = 0; k < 24; k++) {
            H[k+1] = H[k] + red[232 + k];
            T[k+1] = T[k] + red[279 - k];
        }

        const float m  = s1 * (1.0f / L_);
        const float d2 = s2 - (float)L_ * m * m;
        const float d3 = s3 - 3.f*m*s2 + 2.f*(float)L_*m*m*m;
        const float d4 = s4 - 4.f*m*s3 + 6.f*m*m*s2 - 3.f*(float)L_*m*m*m*m;

        const float var  = d2 / (float)(L_ - 1);
        const float stdv = sqrtf(var);
        const float se   = stdv + 1e-8f;
        const float se2  = se * se;
        const float skew = (d3 / (float)L_) / (se * se2 + 1e-8f);
        const float kurt = (d4 / (float)L_) / (se2 * se2 + 1e-8f) - 3.0f;

        const float total = S / (float)FBINS + 1e-8f;
        float lvlsum[3] = { topv[0]+topv[1]+topv[2]+topv[3]+topv[4],
                            topv[5]+topv[6], topv[7] };
        float g[3]; float prefix = 0.f;
        #pragma unroll
        for (int l = 0; l < 3; l++) {
            float rr = ((S - prefix) / (float)FBINS) / total;
            float lr = 0.25f * (float)(l + 1);
            float o = b2v[0];
            #pragma unroll
            for (int j = 0; j < 8; j++) {
                float h = rr * w1[j] + lr * w1[8 + j] + b1v[j];
                h = 0.5f * h * (1.0f + erff(h * 0.70710678118654752f));
                o += h * w2[j];
            }
            g[l] = 1.0f / (1.0f + expf(-o));
            prefix += lvlsum[l];
        }
        const float r1 = g[0], r2 = g[0]*g[1], r3 = g[0]*g[1]*g[2];
        const float rf[9] = {1.f,1.f,1.f,1.f,1.f, r1, r1, r2, r3};
        float cv[9]; int ci[9];
        #pragma unroll
        for (int i = 0; i < 9; i++) { cv[i] = topv[i]*rf[i]; ci[i] = topi[i]; }
        for (int i = 1; i < 9; i++) {           // value desc, index asc on ties
            float v = cv[i]; int id = ci[i]; int j = i - 1;
            while (j >= 0 && (cv[j] < v || (cv[j] == v && ci[j] > id))) {
                cv[j+1] = cv[j]; ci[j+1] = ci[j]; j--;
            }
            cv[j+1] = v; ci[j+1] = id;
        }

        const float invden = 1.0f / (maxamp + 2e-8f);
        float* op = out + (size_t)blockIdx.x * 19;
        op[0] = m; op[1] = stdv; op[2] = skew; op[3] = kurt;
        #pragma unroll
        for (int i = 0; i < 5; i++) {
            op[4 + i] = (float)ci[i] * (1.0f / (float)L_);
            op[9 + i] = cv[i] * invden;
        }
        #pragma unroll
        for (int q = 0; q < 5; q++) {
            int l = lags[q];
            float acsum = R[q] - m * ((s1 - T[l]) + (s1 - H[l])) + (float)(L_ - l) * m * m;
            op[14 + q] = (acsum / (float)(L_ - l)) / se2;
        }
    }
}

// ---------------------------------------------------------------------------
extern "C" void kernel_launch(void* const* d_in, const int* in_sizes, int n_in,
                              void* d_out, int out_size) {
    const float* x  = (const float*)d_in[0];
    const float* w1 = (const float*)d_in[1];
    const float* b1 = (const float*)d_in[2];
    const float* w2 = (const float*)d_in[3];
    const float* b2 = (const float*)d_in[4];
    float* out = (float*)d_out;

    dim3 tb(32, 8);
    dim3 tg(L_ / 32, N_ / 32, B_);
    transpose_kernel<<<tg, tb>>>(x);

    feat_kernel<<<NSERIES, NT>>>(w1, b1, w2, b2, out);
}

// round 10
// speedup vs baseline: 1.0736x; 1.0736x over previous
#include <cuda_runtime.h>
#include <math.h>

#define B_ 32
#define L_ 4096
#define N_ 256
#define NF 2048          // packed complex FFT size (L/2)
#define FBINS 2049       // rfft bins
#define NT 256
#define NSERIES (B_*N_)

typedef unsigned long long u64;

__device__ float  g_xt[(size_t)B_*N_*L_];   // (B,N,L) transposed input
__device__ float2 g_tw[NF/2];               // exp(-2*pi*i*j/2048)
__device__ float2 g_rot[NF];                // exp(-pi*i*k/2048)

// XOR swizzle on float2 indices: conflict-free smem FFT exchanges
#define FZ(a) ((a) ^ (((a) >> 3) & 0xF))
// padded natural-order spectrum index
#define YA(k) ((k) + ((k) >> 3))

// packed candidate: value desc, key asc in ONE u64 compare (amps >= 0)
__device__ __forceinline__ u64 packcand(float v, int k) {
    return ((u64)__float_as_uint(v) << 32) | (unsigned)(0x7fffffff ^ k);
}

__device__ __forceinline__ float2 cmul(float2 a, float2 b) {
    return make_float2(a.x*b.x - a.y*b.y, a.x*b.y + a.y*b.x);
}
__device__ __forceinline__ float2 cadd(float2 a, float2 b) { return make_float2(a.x+b.x, a.y+b.y); }
__device__ __forceinline__ float2 csub(float2 a, float2 b) { return make_float2(a.x-b.x, a.y-b.y); }
__device__ __forceinline__ float2 cnegi(float2 a) { return make_float2(a.y, -a.x); }  // a * (-i)

// ---------------------------------------------------------------------------
// Tiled transpose x (B,L,N) -> g_xt (B,N,L); block (0,0,0) also fills twiddle tables.
__global__ void transpose_kernel(const float* __restrict__ x) {
    __shared__ float tile[32][33];
    int b  = blockIdx.z;
    int l0 = blockIdx.x << 5;
    int n0 = blockIdx.y << 5;
    int tx = threadIdx.x, ty = threadIdx.y;   // (32, 8)
    if (blockIdx.x == 0 && blockIdx.y == 0 && blockIdx.z == 0) {
        int tid = ty * 32 + tx;
        for (int i = tid; i < NF/2; i += 256) {
            float ang = -6.2831853071795864769f * (float)i / (float)NF;
            float sn, cs; sincosf(ang, &sn, &cs);
            g_tw[i] = make_float2(cs, sn);
        }
        for (int i = tid; i < NF; i += 256) {
            float ang = -3.1415926535897932385f * (float)i / (float)NF;
            float sn, cs; sincosf(ang, &sn, &cs);
            g_rot[i] = make_float2(cs, sn);
        }
    }
    #pragma unroll
    for (int i = 0; i < 32; i += 8)
        tile[ty + i][tx] = x[((size_t)b * L_ + (l0 + ty + i)) * N_ + n0 + tx];
    __syncthreads();
    #pragma unroll
    for (int i = 0; i < 32; i += 8)
        g_xt[((size_t)b * N_ + (n0 + ty + i)) * L_ + l0 + tx] = tile[tx][ty + i];
}

// ---------------------------------------------------------------------------
// radix-4 DIF butterfly (in-place digit placement)
__device__ __forceinline__ void bfy4(float2* x, float2 wa, float2 wb) {
    float2 wami = cnegi(wa);
    float2 t0 = cadd(x[0], x[2]), u0 = cmul(csub(x[0], x[2]), wa);
    float2 t1 = cadd(x[1], x[3]), u1 = cmul(csub(x[1], x[3]), wami);
    x[0] = cadd(t0, t1); x[1] = cmul(csub(t0, t1), wb);
    x[2] = cadd(u0, u1); x[3] = cmul(csub(u0, u1), wb);
}

// radix-8 DIF butterfly = 3 in-place radix-2 stages on 8 register values.
__device__ __forceinline__ void bfy8(float2* x, float2 wa, float2 wb, float2 wc) {
    const float R2 = 0.70710678118654752440f;
    float2 wa1 = cmul(wa, make_float2(R2, -R2));
    float2 wa2 = cnegi(wa);
    float2 wa3 = cnegi(wa1);
    float2 wbi = cnegi(wb);
    float2 d;
    d = csub(x[0], x[4]); x[0] = cadd(x[0], x[4]); x[4] = cmul(d, wa);
    d = csub(x[1], x[5]); x[1] = cadd(x[1], x[5]); x[5] = cmul(d, wa1);
    d = csub(x[2], x[6]); x[2] = cadd(x[2], x[6]); x[6] = cmul(d, wa2);
    d = csub(x[3], x[7]); x[3] = cadd(x[3], x[7]); x[7] = cmul(d, wa3);
    d = csub(x[0], x[2]); x[0] = cadd(x[0], x[2]); x[2] = cmul(d, wb);
    d = csub(x[1], x[3]); x[1] = cadd(x[1], x[3]); x[3] = cmul(d, wbi);
    d = csub(x[4], x[6]); x[4] = cadd(x[4], x[6]); x[6] = cmul(d, wb);
    d = csub(x[5], x[7]); x[5] = cadd(x[5], x[7]); x[7] = cmul(d, wbi);
    d = csub(x[0], x[1]); x[0] = cadd(x[0], x[1]); x[1] = cmul(d, wc);
    d = csub(x[2], x[3]); x[2] = cadd(x[2], x[3]); x[3] = cmul(d, wc);
    d = csub(x[4], x[5]); x[4] = cadd(x[4], x[5]); x[5] = cmul(d, wc);
    d = csub(x[6], x[7]); x[6] = cadd(x[6], x[7]); x[7] = cmul(d, wc);
}

// ---------------------------------------------------------------------------
// One CTA per (b,n) series.
__global__ __launch_bounds__(NT, 4) void feat_kernel(
    const float* __restrict__ w1, const float* __restrict__ b1v,
    const float* __restrict__ w2, const float* __restrict__ b2v,
    float* __restrict__ out)
{
    __shared__ __align__(16) u64 sl[2304];  // aliased: [0,4608) floats = series / FFT z[]; later u64 lists
    __shared__ float2 ys[2304];  // natural-order spectrum, interleaved (YA padding)
    __shared__ u64   wl[81];     // 8 warp top-9 lists + global top-9
    __shared__ float red[304];
    // red: [0..71] 9x8 moment partials | [72..79] ampsum | [80..87] ampmax
    //      [232..255] head24 | [256..279] tail24

    float* s = (float*)sl;
    const int tid  = threadIdx.x;
    const int lane = tid & 31, warp = tid >> 5;
    const int lags[5] = {1, 3, 6, 12, 24};

    // ---- phase 1: contiguous load, STS, raw moments in registers ----
    float xl[16];
    {
        const float4* __restrict__ src4 =
            (const float4*)(g_xt + (size_t)blockIdx.x * L_ + tid * 16);
        float4* sm4 = (float4*)s;
        #pragma unroll
        for (int c = 0; c < 4; ++c) {
            float4 v = src4[c];
            sm4[tid*4 + c] = v;
            xl[4*c+0] = v.x; xl[4*c+1] = v.y; xl[4*c+2] = v.z; xl[4*c+3] = v.w;
        }
    }
    if (tid < 8) ((float4*)s)[1024 + tid] = make_float4(0.f, 0.f, 0.f, 0.f); // zero pad

    // edge stashes (raw values) for autocorr boundary terms
    if (tid == 0) {
        for (int k = 0; k < 16; k++) red[232 + k] = xl[k];
    }
    if (tid == 1) {
        for (int k = 0; k < 8;  k++) red[248 + k] = xl[k];
    }
    if (tid == 254) {
        for (int k = 0; k < 8;  k++) red[256 + k] = xl[8 + k];
    }
    if (tid == 255) {
        for (int k = 0; k < 16; k++) red[264 + k] = xl[k];
    }

    float acc[9];   // s1 s2 s3 s4 R1 R3 R6 R12 R24 (raw sums)
    #pragma unroll
    for (int q = 0; q < 9; q++) acc[q] = 0.f;
    #pragma unroll
    for (int i = 0; i < 16; i++) {
        float v = xl[i], v2 = v*v;
        acc[0] += v; acc[1] += v2; acc[2] += v2*v; acc[3] += v2*v2;
        #pragma unroll
        for (int q = 0; q < 5; q++) {
            int j = i + lags[q];
            if (j < 16) acc[4+q] += v * xl[j];
        }
    }
    __syncthreads();   // sync 1: smem series complete (incl. zero pad)

    // cross-boundary lag products: consume tail in float4 chunks
    {
        #pragma unroll
        for (int c2 = 0; c2 < 6; ++c2) {
            float4 v = *(const float4*)(s + tid*16 + 16 + 4*c2);
            float tl4[4] = {v.x, v.y, v.z, v.w};
            #pragma unroll
            for (int q = 0; q < 5; q++) {
                int l = lags[q];
                #pragma unroll
                for (int kk = 0; kk < 4; kk++) {
                    int k = 4*c2 + kk;
                    int i = 16 + k - l;
                    if (k < l && i >= 0) acc[4+q] += xl[i] * tl4[kk];
                }
            }
        }
    }
    // warp-reduce 9 raw sums -> red partials (finalized by tid0 at the end)
    #pragma unroll
    for (int q = 0; q < 9; q++) {
        float v = acc[q];
        #pragma unroll
        for (int o = 16; o > 0; o >>= 1) v += __shfl_down_sync(~0u, v, o);
        if (lane == 0) red[q*8 + warp] = v;
    }

    // ---- FFT group 0: radix-4 (S=2048), natural read -> swizzled write ----
    float2* z = (float2*)s;
    float2 xa[4], xb[4];
    #pragma unroll
    for (int j = 0; j < 4; j++) { xa[j] = z[tid + 512*j]; xb[j] = z[tid + 256 + 512*j]; }
    bfy4(xa, g_tw[tid],       g_tw[2*tid]);
    bfy4(xb, g_tw[tid + 256], g_tw[2*tid + 512]);
    __syncthreads();   // sync 2
    #pragma unroll
    for (int j = 0; j < 4; j++) {
        z[FZ(tid + 512*j)]       = xa[j];
        z[FZ(tid + 256 + 512*j)] = xb[j];
    }
    __syncthreads();   // sync 3

    float2 zx[8];
    // ---- group 1: radix-8, S=512, q=64 ----
    {
        int o = tid & 63, base = (tid >> 6) * 512 + o;
        #pragma unroll
        for (int j = 0; j < 8; j++) zx[j] = z[FZ(base + 64*j)];
        bfy8(zx, g_tw[4*o], g_tw[8*o], g_tw[16*o]);
        #pragma unroll
        for (int j = 0; j < 8; j++) z[FZ(base + 64*j)] = zx[j];
    }
    __syncthreads();   // sync 4
    // ---- group 2: radix-8, S=64, q=8 ----
    {
        int o = tid & 7, base = (tid >> 3) * 64 + o;
        #pragma unroll
        for (int j = 0; j < 8; j++) zx[j] = z[FZ(base + 8*j)];
        bfy8(zx, g_tw[32*o], g_tw[64*o], g_tw[128*o]);
        #pragma unroll
        for (int j = 0; j < 8; j++) z[FZ(base + 8*j)] = zx[j];
    }
    __syncthreads();   // sync 5
    // ---- group 3: radix-8, S=8, q=1 (unit twiddles), fused de-reversal:
    //      outputs go straight to natural-order interleaved ys ----
    {
        int base = tid * 8;
        const float2 one = make_float2(1.f, 0.f);
        #pragma unroll
        for (int j = 0; j < 8; j++) zx[j] = z[FZ(base + j)];
        bfy8(zx, one, one, one);
        #pragma unroll
        for (int j = 0; j < 8; j++) {
            int k = __brev((unsigned)(base + j)) >> 21;   // natural bin
            ys[YA(k)] = zx[j];
        }
    }
    __syncthreads();   // sync 6: ys ready; all z reads done (s/sl reusable)

    // ---- unpack amplitudes via conjugate-pair symmetry, packed candidates ----
    u64 pk[9];
    float Ssum = 0.f, Smax = 0.f;
    #pragma unroll
    for (int c = 0; c < 4; ++c) {
        int k = 1 + tid + 256*c;          // 1..1024
        int m = 2048 - k;                 // 1024..2047
        float2 Zk = ys[YA(k)];
        float2 Zm = ys[YA(m)];
        float er  = 0.5f * (Zk.x + Zm.x);
        float ei  = 0.5f * (Zk.y - Zm.y);
        float orr = 0.5f * (Zk.y + Zm.y);
        float oi  = -0.5f * (Zk.x - Zm.x);
        float2 w = g_rot[k];
        float pr = w.x*orr - w.y*oi;
        float pi = w.x*oi  + w.y*orr;
        float xr = er + pr, xi2 = ei + pi;
        float ampk = sqrtf(xr*xr + xi2*xi2);
        float qr = er - pr, qi = ei - pi;
        float ampm = sqrtf(qr*qr + qi*qi);
        pk[c] = packcand(ampk, k);
        Ssum += ampk; Smax = fmaxf(Smax, ampk);
        if (k == 1024) { pk[4+c] = 0ull; }   // self-pair duplicate
        else {
            pk[4+c] = packcand(ampm, m);
            Ssum += ampm; Smax = fmaxf(Smax, ampm);
        }
    }
    pk[8] = 0ull;

    u64 c0 = 0ull, cN = 0ull;
    if (tid == 0) {
        float2 Z0 = ys[0];                // YA(0)==0
        float a0 = fabsf(Z0.x + Z0.y);    // bin 0
        float aN = fabsf(Z0.x - Z0.y);    // bin 2048
        c0 = packcand(a0, 0); cN = packcand(aN, 2048);
        Ssum += a0 + aN;
        Smax = fmaxf(Smax, fmaxf(a0, aN));
    }

    // sort pk[0..7] descending (packed order = value desc, key asc), Batcher
    #define CE(i,j) { if (pk[i] < pk[j]) { u64 t=pk[i]; pk[i]=pk[j]; pk[j]=t; } }
    CE(0,1) CE(2,3) CE(4,5) CE(6,7)
    CE(0,2) CE(1,3) CE(4,6) CE(5,7)
    CE(1,2) CE(5,6)
    CE(0,4) CE(1,5) CE(2,6) CE(3,7)
    CE(2,4) CE(3,5)
    CE(1,2) CE(3,4) CE(5,6)
    // tid0: insert bins 0 and 2048 (insert-with-drop keeps thread top-9)
    if (tid == 0) {
        if (c0 > pk[8]) pk[8] = c0;
        CE(7,8) CE(6,7) CE(5,6) CE(4,5) CE(3,4) CE(2,3) CE(1,2) CE(0,1)
        if (cN > pk[8]) pk[8] = cN;
        CE(7,8) CE(6,7) CE(5,6) CE(4,5) CE(3,4) CE(2,3) CE(1,2) CE(0,1)
    } else {
        CE(7,8) CE(6,7) CE(5,6) CE(4,5) CE(3,4) CE(2,3) CE(1,2) CE(0,1)
    }
    #undef CE

    // amp sum/max warp partials
    {
        float sv = Ssum, mv = Smax;
        #pragma unroll
        for (int o = 16; o > 0; o >>= 1) {
            sv += __shfl_down_sync(~0u, sv, o);
            mv = fmaxf(mv, __shfl_down_sync(~0u, mv, o));
        }
        if (lane == 0) { red[72 + warp] = sv; red[80 + warp] = mv; }
    }

    // spill per-thread sorted u64 lists (sl dead since sync 6; each thread
    // writes + reads only its own slots — no barrier needed for Phase A)
    #pragma unroll
    for (int r = 0; r < 9; ++r) sl[tid*9 + r] = pk[r];

    // ---- Phase A: warp-local tournament -> warp top-9 ----
    {
        int p = 0;
        #pragma unroll
        for (int r = 0; r < 9; ++r) {
            u64 h = (p < 9) ? sl[tid*9 + p] : 0ull;
            u64 b = h;
            #pragma unroll
            for (int o = 16; o > 0; o >>= 1) {
                u64 ob = __shfl_down_sync(~0u, b, o);
                if (ob > b) b = ob;
            }
            u64 wb = __shfl_sync(~0u, b, 0);
            if (h == wb && h != 0ull) p++;
            if (lane == 0) wl[warp*9 + r] = wb;
        }
    }
    __syncthreads();   // sync 7: warp winners + amp partials visible

    // ---- Phase B: warp 0 merges 8 warp lists -> global top-9 ----
    if (warp == 0) {
        int p = 0;
        #pragma unroll
        for (int r = 0; r < 9; ++r) {
            u64 h = (lane < 8 && p < 9) ? wl[lane*9 + p] : 0ull;
            u64 b = h;
            #pragma unroll
            for (int o = 4; o > 0; o >>= 1) {
                u64 ob = __shfl_down_sync(~0u, b, o);
                if (ob > b) b = ob;
            }
            u64 wb = __shfl_sync(~0u, b, 0);
            if (h == wb && h != 0ull) p++;
            if (lane == 0) wl[72 + r] = wb;
        }
    }

    // ---- epilogue (thread 0, same warp as Phase B writes) ----
    if (tid == 0) {
        float s1 = 0.f, s2 = 0.f, s3 = 0.f, s4 = 0.f, R[5] = {0,0,0,0,0};
        float S = 0.f, maxamp = 0.f;
        #pragma unroll
        for (int i = 0; i < 8; i++) {
            s1 += red[0*8+i]; s2 += red[1*8+i]; s3 += red[2*8+i]; s4 += red[3*8+i];
            R[0] += red[4*8+i]; R[1] += red[5*8+i]; R[2] += red[6*8+i];
            R[3] += red[7*8+i]; R[4] += red[8*8+i];
            S += red[72+i]; maxamp = fmaxf(maxamp, red[80+i]);
        }
        float topv[9]; int topi[9];
        #pragma unroll
        for (int r = 0; r < 9; ++r) {
            u64 w = wl[72 + r];
            topv[r] = __uint_as_float((unsigned)(w >> 32));
            topi[r] = 0x7fffffff ^ (int)(unsigned)w;
        }
        // edge prefix/suffix sums
        float H[25], T[25];
        H[0] = 0.f; T[0] = 0.f;
        #pragma unroll
        for (int k = 0; k < 24; k++) {
            H[k+1] = H[k] + red[232 + k];
            T[k+1] = T[k] + red[279 - k];
        }

        const float m  = s1 * (1.0f / L_);
        const float d2 = s2 - (float)L_ * m * m;
        const float d3 = s3 - 3.f*m*s2 + 2.f*(float)L_*m*m*m;
        const float d4 = s4 - 4.f*m*s3 + 6.f*m*m*s2 - 3.f*(float)L_*m*m*m*m;

        const float var  = d2 / (float)(L_ - 1);
        const float stdv = sqrtf(var);
        const float se   = stdv + 1e-8f;
        const float se2  = se * se;
        const float skew = (d3 / (float)L_) / (se * se2 + 1e-8f);
        const float kurt = (d4 / (float)L_) / (se2 * se2 + 1e-8f) - 3.0f;

        const float total = S / (float)FBINS + 1e-8f;
        float lvlsum[3] = { topv[0]+topv[1]+topv[2]+topv[3]+topv[4],
                            topv[5]+topv[6], topv[7] };
        float g[3]; float prefix = 0.f;
        #pragma unroll
        for (int l = 0; l < 3; l++) {
            float rr = ((S - prefix) / (float)FBINS) / total;
            float lr = 0.25f * (float)(l + 1);
            float o = b2v[0];
            #pragma unroll
            for (int j = 0; j < 8; j++) {
                float h = rr * w1[j] + lr * w1[8 + j] + b1v[j];
                h = 0.5f * h * (1.0f + erff(h * 0.70710678118654752f));
                o += h * w2[j];
            }
            g[l] = 1.0f / (1.0f + expf(-o));
            prefix += lvlsum[l];
        }
        const float r1 = g[0], r2 = g[0]*g[1], r3 = g[0]*g[1]*g[2];
        const float rf[9] = {1.f,1.f,1.f,1.f,1.f, r1, r1, r2, r3};
        float cv[9]; int ci[9];
        #pragma unroll
        for (int i = 0; i < 9; i++) { cv[i] = topv[i]*rf[i]; ci[i] = topi[i]; }
        for (int i = 1; i < 9; i++) {           // value desc, index asc on ties
            float v = cv[i]; int id = ci[i]; int j = i - 1;
            while (j >= 0 && (cv[j] < v || (cv[j] == v && ci[j] > id))) {
                cv[j+1] = cv[j]; ci[j+1] = ci[j]; j--;
            }
            cv[j+1] = v; ci[j+1] = id;
        }

        const float invden = 1.0f / (maxamp + 2e-8f);
        float* op = out + (size_t)blockIdx.x * 19;
        op[0] = m; op[1] = stdv; op[2] = skew; op[3] = kurt;
        #pragma unroll
        for (int i = 0; i < 5; i++) {
            op[4 + i] = (float)ci[i] * (1.0f / (float)L_);
            op[9 + i] = cv[i] * invden;
        }
        const int lags2[5] = {1, 3, 6, 12, 24};
        #pragma unroll
        for (int q = 0; q < 5; q++) {
            int l = lags2[q];
            float acsum = R[q] - m * ((s1 - T[l]) + (s1 - H[l])) + (float)(L_ - l) * m * m;
            op[14 + q] = (acsum / (float)(L_ - l)) / se2;
        }
    }
}

// ---------------------------------------------------------------------------
extern "C" void kernel_launch(void* const* d_in, const int* in_sizes, int n_in,
                              void* d_out, int out_size) {
    const float* x  = (const float*)d_in[0];
    const float* w1 = (const float*)d_in[1];
    const float* b1 = (const float*)d_in[2];
    const float* w2 = (const float*)d_in[3];
    const float* b2 = (const float*)d_in[4];
    float* out = (float*)d_out;

    dim3 tb(32, 8);
    dim3 tg(L_ / 32, N_ / 32, B_);
    transpose_kernel<<<tg, tb>>>(x);

    feat_kernel<<<NSERIES, NT>>>(w1, b1, w2, b2, out);
}

// round 11
// speedup vs baseline: 1.0744x; 1.0008x over previous
#include <cuda_runtime.h>
#include <math.h>

#define B_ 32
#define L_ 4096
#define N_ 256
#define NF 2048          // packed complex FFT size (L/2)
#define FBINS 2049       // rfft bins
#define NT 256
#define NSERIES (B_*N_)

typedef unsigned long long u64;

__device__ float  g_xt[(size_t)B_*N_*L_];   // (B,N,L) transposed input
__device__ float2 g_tw[NF/2];               // exp(-2*pi*i*j/2048)
__device__ float2 g_rot[NF];                // exp(-pi*i*k/2048)

// XOR swizzle on float2 indices: conflict-free smem FFT exchanges
#define FZ(a) ((a) ^ (((a) >> 3) & 0xF))
// padded natural-order spectrum index
#define YA(k) ((k) + ((k) >> 3))

// packed candidate: value desc, key asc in ONE u64 compare (amps >= 0)
__device__ __forceinline__ u64 packcand(float v, int k) {
    return ((u64)__float_as_uint(v) << 32) | (unsigned)(0x7fffffff ^ k);
}

__device__ __forceinline__ float2 cmul(float2 a, float2 b) {
    return make_float2(a.x*b.x - a.y*b.y, a.x*b.y + a.y*b.x);
}
__device__ __forceinline__ float2 cadd(float2 a, float2 b) { return make_float2(a.x+b.x, a.y+b.y); }
__device__ __forceinline__ float2 csub(float2 a, float2 b) { return make_float2(a.x-b.x, a.y-b.y); }
__device__ __forceinline__ float2 cnegi(float2 a) { return make_float2(a.y, -a.x); }  // a * (-i)

// ---------------------------------------------------------------------------
// Tiled transpose x (B,L,N) -> g_xt (B,N,L); block (0,0,0) also fills twiddle tables.
__global__ void transpose_kernel(const float* __restrict__ x) {
    __shared__ float tile[32][33];
    int b  = blockIdx.z;
    int l0 = blockIdx.x << 5;
    int n0 = blockIdx.y << 5;
    int tx = threadIdx.x, ty = threadIdx.y;   // (32, 8)
    if (blockIdx.x == 0 && blockIdx.y == 0 && blockIdx.z == 0) {
        int tid = ty * 32 + tx;
        for (int i = tid; i < NF/2; i += 256) {
            float ang = -6.2831853071795864769f * (float)i / (float)NF;
            float sn, cs; sincosf(ang, &sn, &cs);
            g_tw[i] = make_float2(cs, sn);
        }
        for (int i = tid; i < NF; i += 256) {
            float ang = -3.1415926535897932385f * (float)i / (float)NF;
            float sn, cs; sincosf(ang, &sn, &cs);
            g_rot[i] = make_float2(cs, sn);
        }
    }
    #pragma unroll
    for (int i = 0; i < 32; i += 8)
        tile[ty + i][tx] = x[((size_t)b * L_ + (l0 + ty + i)) * N_ + n0 + tx];
    __syncthreads();
    #pragma unroll
    for (int i = 0; i < 32; i += 8)
        g_xt[((size_t)b * N_ + (n0 + ty + i)) * L_ + l0 + tx] = tile[tx][ty + i];
}

// ---------------------------------------------------------------------------
// radix-4 DIF butterfly (in-place digit placement)
__device__ __forceinline__ void bfy4(float2* x, float2 wa, float2 wb) {
    float2 wami = cnegi(wa);
    float2 t0 = cadd(x[0], x[2]), u0 = cmul(csub(x[0], x[2]), wa);
    float2 t1 = cadd(x[1], x[3]), u1 = cmul(csub(x[1], x[3]), wami);
    x[0] = cadd(t0, t1); x[1] = cmul(csub(t0, t1), wb);
    x[2] = cadd(u0, u1); x[3] = cmul(csub(u0, u1), wb);
}

// radix-8 DIF butterfly = 3 in-place radix-2 stages on 8 register values.
__device__ __forceinline__ void bfy8(float2* x, float2 wa, float2 wb, float2 wc) {
    const float R2 = 0.70710678118654752440f;
    float2 wa1 = cmul(wa, make_float2(R2, -R2));
    float2 wa2 = cnegi(wa);
    float2 wa3 = cnegi(wa1);
    float2 wbi = cnegi(wb);
    float2 d;
    d = csub(x[0], x[4]); x[0] = cadd(x[0], x[4]); x[4] = cmul(d, wa);
    d = csub(x[1], x[5]); x[1] = cadd(x[1], x[5]); x[5] = cmul(d, wa1);
    d = csub(x[2], x[6]); x[2] = cadd(x[2], x[6]); x[6] = cmul(d, wa2);
    d = csub(x[3], x[7]); x[3] = cadd(x[3], x[7]); x[7] = cmul(d, wa3);
    d = csub(x[0], x[2]); x[0] = cadd(x[0], x[2]); x[2] = cmul(d, wb);
    d = csub(x[1], x[3]); x[1] = cadd(x[1], x[3]); x[3] = cmul(d, wbi);
    d = csub(x[4], x[6]); x[4] = cadd(x[4], x[6]); x[6] = cmul(d, wb);
    d = csub(x[5], x[7]); x[5] = cadd(x[5], x[7]); x[7] = cmul(d, wbi);
    d = csub(x[0], x[1]); x[0] = cadd(x[0], x[1]); x[1] = cmul(d, wc);
    d = csub(x[2], x[3]); x[2] = cadd(x[2], x[3]); x[3] = cmul(d, wc);
    d = csub(x[4], x[5]); x[4] = cadd(x[4], x[5]); x[5] = cmul(d, wc);
    d = csub(x[6], x[7]); x[6] = cadd(x[6], x[7]); x[7] = cmul(d, wc);
}

// ---------------------------------------------------------------------------
// One CTA per (b,n) series.
__global__ __launch_bounds__(NT, 4) void feat_kernel(
    const float* __restrict__ w1, const float* __restrict__ b1v,
    const float* __restrict__ w2, const float* __restrict__ b2v,
    float* __restrict__ out)
{
    __shared__ __align__(16) u64 sl[2304];  // aliased: [0,4608) floats = series / FFT z[]; later u64 lists
    __shared__ float2 ys[2304];  // g0 ping-pong scratch; later natural-order spectrum (YA padding)
    __shared__ u64   wl[81];     // 8 warp top-9 lists + global top-9
    __shared__ float red[304];
    // red: [0..71] 9x8 moment partials | [72..79] ampsum | [80..87] ampmax
    //      [232..255] head24 | [256..279] tail24

    float* s = (float*)sl;
    const int tid  = threadIdx.x;
    const int lane = tid & 31, warp = tid >> 5;
    const int lags[5] = {1, 3, 6, 12, 24};

    // ---- phase 1: contiguous load, STS, raw moments in registers ----
    float xl[16];
    {
        const float4* __restrict__ src4 =
            (const float4*)(g_xt + (size_t)blockIdx.x * L_ + tid * 16);
        float4* sm4 = (float4*)s;
        #pragma unroll
        for (int c = 0; c < 4; ++c) {
            float4 v = src4[c];
            sm4[tid*4 + c] = v;
            xl[4*c+0] = v.x; xl[4*c+1] = v.y; xl[4*c+2] = v.z; xl[4*c+3] = v.w;
        }
    }
    if (tid < 8) ((float4*)s)[1024 + tid] = make_float4(0.f, 0.f, 0.f, 0.f); // zero pad

    // edge stashes (raw values) for autocorr boundary terms
    if (tid == 0) {
        for (int k = 0; k < 16; k++) red[232 + k] = xl[k];
    }
    if (tid == 1) {
        for (int k = 0; k < 8;  k++) red[248 + k] = xl[k];
    }
    if (tid == 254) {
        for (int k = 0; k < 8;  k++) red[256 + k] = xl[8 + k];
    }
    if (tid == 255) {
        for (int k = 0; k < 16; k++) red[264 + k] = xl[k];
    }

    float acc[9];   // s1 s2 s3 s4 R1 R3 R6 R12 R24 (raw sums)
    #pragma unroll
    for (int q = 0; q < 9; q++) acc[q] = 0.f;
    #pragma unroll
    for (int i = 0; i < 16; i++) {
        float v = xl[i], v2 = v*v;
        acc[0] += v; acc[1] += v2; acc[2] += v2*v; acc[3] += v2*v2;
        #pragma unroll
        for (int q = 0; q < 5; q++) {
            int j = i + lags[q];
            if (j < 16) acc[4+q] += v * xl[j];
        }
    }
    __syncthreads();   // sync 1: smem series complete (incl. zero pad)

    // cross-boundary lag products: consume tail in float4 chunks
    {
        #pragma unroll
        for (int c2 = 0; c2 < 6; ++c2) {
            float4 v = *(const float4*)(s + tid*16 + 16 + 4*c2);
            float tl4[4] = {v.x, v.y, v.z, v.w};
            #pragma unroll
            for (int q = 0; q < 5; q++) {
                int l = lags[q];
                #pragma unroll
                for (int kk = 0; kk < 4; kk++) {
                    int k = 4*c2 + kk;
                    int i = 16 + k - l;
                    if (k < l && i >= 0) acc[4+q] += xl[i] * tl4[kk];
                }
            }
        }
    }
    // warp-reduce 9 raw sums -> red partials (finalized by tid0 at the end)
    #pragma unroll
    for (int q = 0; q < 9; q++) {
        float v = acc[q];
        #pragma unroll
        for (int o = 16; o > 0; o >>= 1) v += __shfl_down_sync(~0u, v, o);
        if (lane == 0) red[q*8 + warp] = v;
    }

    // ---- FFT group 0: radix-4 (S=2048), read z natural -> write ys swizzled.
    //      Different buffers: no WAR barrier needed between read and write. ----
    float2* z = (float2*)s;
    float2 xa[4], xb[4];
    #pragma unroll
    for (int j = 0; j < 4; j++) { xa[j] = z[tid + 512*j]; xb[j] = z[tid + 256 + 512*j]; }
    bfy4(xa, g_tw[tid],       g_tw[2*tid]);
    bfy4(xb, g_tw[tid + 256], g_tw[2*tid + 512]);
    #pragma unroll
    for (int j = 0; j < 4; j++) {
        ys[FZ(tid + 512*j)]       = xa[j];
        ys[FZ(tid + 256 + 512*j)] = xb[j];
    }
    __syncthreads();   // sync 2: g0 output ready in ys

    float2 zx[8];
    // ---- group 1: radix-8, S=512, q=64 (reads ys, writes z) ----
    {
        int o = tid & 63, base = (tid >> 6) * 512 + o;
        #pragma unroll
        for (int j = 0; j < 8; j++) zx[j] = ys[FZ(base + 64*j)];
        bfy8(zx, g_tw[4*o], g_tw[8*o], g_tw[16*o]);
        #pragma unroll
        for (int j = 0; j < 8; j++) z[FZ(base + 64*j)] = zx[j];
    }
    __syncthreads();   // sync 3
    // ---- group 2: radix-8, S=64, q=8 (in-place per-thread) ----
    {
        int o = tid & 7, base = (tid >> 3) * 64 + o;
        #pragma unroll
        for (int j = 0; j < 8; j++) zx[j] = z[FZ(base + 8*j)];
        bfy8(zx, g_tw[32*o], g_tw[64*o], g_tw[128*o]);
        #pragma unroll
        for (int j = 0; j < 8; j++) z[FZ(base + 8*j)] = zx[j];
    }
    __syncthreads();   // sync 4
    // ---- group 3: radix-8, S=8, q=1 (unit twiddles), fused de-reversal:
    //      outputs go straight to natural-order interleaved ys ----
    {
        int base = tid * 8;
        const float2 one = make_float2(1.f, 0.f);
        #pragma unroll
        for (int j = 0; j < 8; j++) zx[j] = z[FZ(base + j)];
        bfy8(zx, one, one, one);
        #pragma unroll
        for (int j = 0; j < 8; j++) {
            int k = __brev((unsigned)(base + j)) >> 21;   // natural bin
            ys[YA(k)] = zx[j];
        }
    }
    __syncthreads();   // sync 5: ys = natural spectrum; all z reads done (s/sl reusable)

    // ---- unpack amplitudes via conjugate-pair symmetry, packed candidates ----
    u64 pk[9];
    float Ssum = 0.f, Smax = 0.f;
    #pragma unroll
    for (int c = 0; c < 4; ++c) {
        int k = 1 + tid + 256*c;          // 1..1024
        int m = 2048 - k;                 // 1024..2047
        float2 Zk = ys[YA(k)];
        float2 Zm = ys[YA(m)];
        float er  = 0.5f * (Zk.x + Zm.x);
        float ei  = 0.5f * (Zk.y - Zm.y);
        float orr = 0.5f * (Zk.y + Zm.y);
        float oi  = -0.5f * (Zk.x - Zm.x);
        float2 w = g_rot[k];
        float pr = w.x*orr - w.y*oi;
        float pi = w.x*oi  + w.y*orr;
        float xr = er + pr, xi2 = ei + pi;
        float ampk = sqrtf(xr*xr + xi2*xi2);
        float qr = er - pr, qi = ei - pi;
        float ampm = sqrtf(qr*qr + qi*qi);
        pk[c] = packcand(ampk, k);
        Ssum += ampk; Smax = fmaxf(Smax, ampk);
        if (k == 1024) { pk[4+c] = 0ull; }   // self-pair duplicate
        else {
            pk[4+c] = packcand(ampm, m);
            Ssum += ampm; Smax = fmaxf(Smax, ampm);
        }
    }
    pk[8] = 0ull;

    u64 c0 = 0ull, cN = 0ull;
    if (tid == 0) {
        float2 Z0 = ys[0];                // YA(0)==0
        float a0 = fabsf(Z0.x + Z0.y);    // bin 0
        float aN = fabsf(Z0.x - Z0.y);    // bin 2048
        c0 = packcand(a0, 0); cN = packcand(aN, 2048);
        Ssum += a0 + aN;
        Smax = fmaxf(Smax, fmaxf(a0, aN));
    }

    // sort pk[0..7] descending (packed order = value desc, key asc), Batcher
    #define CE(i,j) { if (pk[i] < pk[j]) { u64 t=pk[i]; pk[i]=pk[j]; pk[j]=t; } }
    CE(0,1) CE(2,3) CE(4,5) CE(6,7)
    CE(0,2) CE(1,3) CE(4,6) CE(5,7)
    CE(1,2) CE(5,6)
    CE(0,4) CE(1,5) CE(2,6) CE(3,7)
    CE(2,4) CE(3,5)
    CE(1,2) CE(3,4) CE(5,6)
    // tid0: insert bins 0 and 2048 (insert-with-drop keeps thread top-9)
    if (tid == 0) {
        if (c0 > pk[8]) pk[8] = c0;
        CE(7,8) CE(6,7) CE(5,6) CE(4,5) CE(3,4) CE(2,3) CE(1,2) CE(0,1)
        if (cN > pk[8]) pk[8] = cN;
        CE(7,8) CE(6,7) CE(5,6) CE(4,5) CE(3,4) CE(2,3) CE(1,2) CE(0,1)
    } else {
        CE(7,8) CE(6,7) CE(5,6) CE(4,5) CE(3,4) CE(2,3) CE(1,2) CE(0,1)
    }
    #undef CE

    // amp sum/max warp partials
    {
        float sv = Ssum, mv = Smax;
        #pragma unroll
        for (int o = 16; o > 0; o >>= 1) {
            sv += __shfl_down_sync(~0u, sv, o);
            mv = fmaxf(mv, __shfl_down_sync(~0u, mv, o));
        }
        if (lane == 0) { red[72 + warp] = sv; red[80 + warp] = mv; }
    }

    // spill per-thread sorted u64 lists (sl dead since sync 5; each thread
    // writes + reads only its own slots — no barrier needed for Phase A)
    #pragma unroll
    for (int r = 0; r < 9; ++r) sl[tid*9 + r] = pk[r];

    // ---- Phase A: warp-local tournament -> warp top-9 (bfly all-reduce max) ----
    {
        int p = 0;
        #pragma unroll
        for (int r = 0; r < 9; ++r) {
            u64 h = (p < 9) ? sl[tid*9 + p] : 0ull;
            u64 b = h;
            #pragma unroll
            for (int o = 16; o > 0; o >>= 1) {
                u64 ob = __shfl_xor_sync(~0u, b, o);
                if (ob > b) b = ob;
            }
            if (h == b && h != 0ull) p++;
            if (lane == 0) wl[warp*9 + r] = b;
        }
    }
    __syncthreads();   // sync 6: warp winners + amp partials visible

    // ---- Phase B: warp 0 merges 8 warp lists -> global top-9 ----
    if (warp == 0) {
        int p = 0;
        #pragma unroll
        for (int r = 0; r < 9; ++r) {
            u64 h = (lane < 8 && p < 9) ? wl[lane*9 + p] : 0ull;
            u64 b = h;
            #pragma unroll
            for (int o = 4; o > 0; o >>= 1) {
                u64 ob = __shfl_xor_sync(~0u, b, o);
                if (ob > b) b = ob;
            }
            if (h == b && h != 0ull) p++;
            if (lane == 0) wl[72 + r] = b;
        }
    }

    // ---- epilogue (thread 0, same warp as Phase B writes) ----
    if (tid == 0) {
        float s1 = 0.f, s2 = 0.f, s3 = 0.f, s4 = 0.f, R[5] = {0,0,0,0,0};
        float S = 0.f, maxamp = 0.f;
        #pragma unroll
        for (int i = 0; i < 8; i++) {
            s1 += red[0*8+i]; s2 += red[1*8+i]; s3 += red[2*8+i]; s4 += red[3*8+i];
            R[0] += red[4*8+i]; R[1] += red[5*8+i]; R[2] += red[6*8+i];
            R[3] += red[7*8+i]; R[4] += red[8*8+i];
            S += red[72+i]; maxamp = fmaxf(maxamp, red[80+i]);
        }
        float topv[9]; int topi[9];
        #pragma unroll
        for (int r = 0; r < 9; ++r) {
            u64 w = wl[72 + r];
            topv[r] = __uint_as_float((unsigned)(w >> 32));
            topi[r] = 0x7fffffff ^ (int)(unsigned)w;
        }
        // edge prefix/suffix sums
        float H[25], T[25];
        H[0] = 0.f; T[0] = 0.f;
        #pragma unroll
        for (int k = 0; k < 24; k++) {
            H[k+1] = H[k] + red[232 + k];
            T[k+1] = T[k] + red[279 - k];
        }

        const float m  = s1 * (1.0f / L_);
        const float d2 = s2 - (float)L_ * m * m;
        const float d3 = s3 - 3.f*m*s2 + 2.f*(float)L_*m*m*m;
        const float d4 = s4 - 4.f*m*s3 + 6.f*m*m*s2 - 3.f*(float)L_*m*m*m*m;

        const float var  = d2 / (float)(L_ - 1);
        const float stdv = sqrtf(var);
        const float se   = stdv + 1e-8f;
        const float se2  = se * se;
        const float skew = (d3 / (float)L_) / (se * se2 + 1e-8f);
        const float kurt = (d4 / (float)L_) / (se2 * se2 + 1e-8f) - 3.0f;

        const float total = S / (float)FBINS + 1e-8f;
        float lvlsum[3] = { topv[0]+topv[1]+topv[2]+topv[3]+topv[4],
                            topv[5]+topv[6], topv[7] };
        float g[3]; float prefix = 0.f;
        #pragma unroll
        for (int l = 0; l < 3; l++) {
            float rr = ((S - prefix) / (float)FBINS) / total;
            float lr = 0.25f * (float)(l + 1);
            float o = b2v[0];
            #pragma unroll
            for (int j = 0; j < 8; j++) {
                float h = rr * w1[j] + lr * w1[8 + j] + b1v[j];
                h = 0.5f * h * (1.0f + erff(h * 0.70710678118654752f));
                o += h * w2[j];
            }
            g[l] = 1.0f / (1.0f + expf(-o));
            prefix += lvlsum[l];
        }
        const float r1 = g[0], r2 = g[0]*g[1], r3 = g[0]*g[1]*g[2];
        const float rf[9] = {1.f,1.f,1.f,1.f,1.f, r1, r1, r2, r3};
        float cv[9]; int ci[9];
        #pragma unroll
        for (int i = 0; i < 9; i++) { cv[i] = topv[i]*rf[i]; ci[i] = topi[i]; }
        for (int i = 1; i < 9; i++) {           // value desc, index asc on ties
            float v = cv[i]; int id = ci[i]; int j = i - 1;
            while (j >= 0 && (cv[j] < v || (cv[j] == v && ci[j] > id))) {
                cv[j+1] = cv[j]; ci[j+1] = ci[j]; j--;
            }
            cv[j+1] = v; ci[j+1] = id;
        }

        const float invden = 1.0f / (maxamp + 2e-8f);
        float* op = out + (size_t)blockIdx.x * 19;
        op[0] = m; op[1] = stdv; op[2] = skew; op[3] = kurt;
        #pragma unroll
        for (int i = 0; i < 5; i++) {
            op[4 + i] = (float)ci[i] * (1.0f / (float)L_);
            op[9 + i] = cv[i] * invden;
        }
        const int lags2[5] = {1, 3, 6, 12, 24};
        #pragma unroll
        for (int q = 0; q < 5; q++) {
            int l = lags2[q];
            float acsum = R[q] - m * ((s1 - T[l]) + (s1 - H[l])) + (float)(L_ - l) * m * m;
            op[14 + q] = (acsum / (float)(L_ - l)) / se2;
        }
    }
}

// ---------------------------------------------------------------------------
extern "C" void kernel_launch(void* const* d_in, const int* in_sizes, int n_in,
                              void* d_out, int out_size) {
    const float* x  = (const float*)d_in[0];
    const float* w1 = (const float*)d_in[1];
    const float* b1 = (const float*)d_in[2];
    const float* w2 = (const float*)d_in[3];
    const float* b2 = (const float*)d_in[4];
    float* out = (float*)d_out;

    dim3 tb(32, 8);
    dim3 tg(L_ / 32, N_ / 32, B_);
    transpose_kernel<<<tg, tb>>>(x);

    feat_kernel<<<NSERIES, NT>>>(w1, b1, w2, b2, out);
}

// round 12
// speedup vs baseline: 1.1029x; 1.0265x over previous
#include <cuda_runtime.h>
#include <math.h>

#define B_ 32
#define L_ 4096
#define N_ 256
#define NF 2048          // packed complex FFT size (L/2)
#define FBINS 2049       // rfft bins
#define NT 256
#define NSERIES (B_*N_)

typedef unsigned long long u64;

__device__ float  g_xt[(size_t)B_*N_*L_];   // (B,N,L) transposed input
__device__ float2 g_tw[NF/2];               // exp(-2*pi*i*j/2048)
__device__ float2 g_rot[NF];                // exp(-pi*i*k/2048)

// XOR swizzle on float2 indices: conflict-free smem FFT exchanges
#define FZ(a) ((a) ^ (((a) >> 3) & 0xF))
// padded natural-order spectrum index
#define YA(k) ((k) + ((k) >> 3))

// packed candidate: value desc, key asc in ONE u64 compare (amps >= 0)
__device__ __forceinline__ u64 packcand(float v, int k) {
    return ((u64)__float_as_uint(v) << 32) | (unsigned)(0x7fffffff ^ k);
}

__device__ __forceinline__ float2 cmul(float2 a, float2 b) {
    return make_float2(a.x*b.x - a.y*b.y, a.x*b.y + a.y*b.x);
}
__device__ __forceinline__ float2 cadd(float2 a, float2 b) { return make_float2(a.x+b.x, a.y+b.y); }
__device__ __forceinline__ float2 csub(float2 a, float2 b) { return make_float2(a.x-b.x, a.y-b.y); }
__device__ __forceinline__ float2 cnegi(float2 a) { return make_float2(a.y, -a.x); }  // a * (-i)

// ---------------------------------------------------------------------------
// Tiled transpose x (B,L,N) -> g_xt (B,N,L); block (0,0,0) also fills twiddle tables.
__global__ void transpose_kernel(const float* __restrict__ x) {
    __shared__ float tile[32][33];
    int b  = blockIdx.z;
    int l0 = blockIdx.x << 5;
    int n0 = blockIdx.y << 5;
    int tx = threadIdx.x, ty = threadIdx.y;   // (32, 8)
    if (blockIdx.x == 0 && blockIdx.y == 0 && blockIdx.z == 0) {
        int tid = ty * 32 + tx;
        for (int i = tid; i < NF/2; i += 256) {
            float ang = -6.2831853071795864769f * (float)i / (float)NF;
            float sn, cs; sincosf(ang, &sn, &cs);
            g_tw[i] = make_float2(cs, sn);
        }
        for (int i = tid; i < NF; i += 256) {
            float ang = -3.1415926535897932385f * (float)i / (float)NF;
            float sn, cs; sincosf(ang, &sn, &cs);
            g_rot[i] = make_float2(cs, sn);
        }
    }
    #pragma unroll
    for (int i = 0; i < 32; i += 8)
        tile[ty + i][tx] = x[((size_t)b * L_ + (l0 + ty + i)) * N_ + n0 + tx];
    __syncthreads();
    #pragma unroll
    for (int i = 0; i < 32; i += 8)
        g_xt[((size_t)b * N_ + (n0 + ty + i)) * L_ + l0 + tx] = tile[tx][ty + i];
}

// ---------------------------------------------------------------------------
// radix-4 DIF butterfly (in-place digit placement)
__device__ __forceinline__ void bfy4(float2* x, float2 wa, float2 wb) {
    float2 wami = cnegi(wa);
    float2 t0 = cadd(x[0], x[2]), u0 = cmul(csub(x[0], x[2]), wa);
    float2 t1 = cadd(x[1], x[3]), u1 = cmul(csub(x[1], x[3]), wami);
    x[0] = cadd(t0, t1); x[1] = cmul(csub(t0, t1), wb);
    x[2] = cadd(u0, u1); x[3] = cmul(csub(u0, u1), wb);
}

// radix-8 DIF butterfly = 3 in-place radix-2 stages on 8 register values.
__device__ __forceinline__ void bfy8(float2* x, float2 wa, float2 wb, float2 wc) {
    const float R2 = 0.70710678118654752440f;
    float2 wa1 = cmul(wa, make_float2(R2, -R2));
    float2 wa2 = cnegi(wa);
    float2 wa3 = cnegi(wa1);
    float2 wbi = cnegi(wb);
    float2 d;
    d = csub(x[0], x[4]); x[0] = cadd(x[0], x[4]); x[4] = cmul(d, wa);
    d = csub(x[1], x[5]); x[1] = cadd(x[1], x[5]); x[5] = cmul(d, wa1);
    d = csub(x[2], x[6]); x[2] = cadd(x[2], x[6]); x[6] = cmul(d, wa2);
    d = csub(x[3], x[7]); x[3] = cadd(x[3], x[7]); x[7] = cmul(d, wa3);
    d = csub(x[0], x[2]); x[0] = cadd(x[0], x[2]); x[2] = cmul(d, wb);
    d = csub(x[1], x[3]); x[1] = cadd(x[1], x[3]); x[3] = cmul(d, wbi);
    d = csub(x[4], x[6]); x[4] = cadd(x[4], x[6]); x[6] = cmul(d, wb);
    d = csub(x[5], x[7]); x[5] = cadd(x[5], x[7]); x[7] = cmul(d, wbi);
    d = csub(x[0], x[1]); x[0] = cadd(x[0], x[1]); x[1] = cmul(d, wc);
    d = csub(x[2], x[3]); x[2] = cadd(x[2], x[3]); x[3] = cmul(d, wc);
    d = csub(x[4], x[5]); x[4] = cadd(x[4], x[5]); x[5] = cmul(d, wc);
    d = csub(x[6], x[7]); x[6] = cadd(x[6], x[7]); x[7] = cmul(d, wc);
}

// ---------------------------------------------------------------------------
// One CTA per (b,n) series.
__global__ __launch_bounds__(NT, 4) void feat_kernel(
    const float* __restrict__ w1, const float* __restrict__ b1v,
    const float* __restrict__ w2, const float* __restrict__ b2v,
    float* __restrict__ out)
{
    __shared__ __align__(16) float s[4608];  // series + zero pad / FFT z[]
    __shared__ float2 ys[2304];  // g0 ping-pong scratch; later natural-order spectrum (YA padding)
    __shared__ u64   wl[81];     // 8 warp top-9 lists + global top-9
    __shared__ float red[304];
    // red: [0..71] 9x8 moment partials | [72..79] ampsum | [80..87] ampmax
    //      [232..255] head24 | [256..279] tail24

    const int tid  = threadIdx.x;
    const int lane = tid & 31, warp = tid >> 5;
    const int lags[5] = {1, 3, 6, 12, 24};

    // ---- phase 1: contiguous load, STS, raw moments in registers ----
    float xl[16];
    {
        const float4* __restrict__ src4 =
            (const float4*)(g_xt + (size_t)blockIdx.x * L_ + tid * 16);
        float4* sm4 = (float4*)s;
        #pragma unroll
        for (int c = 0; c < 4; ++c) {
            float4 v = src4[c];
            sm4[tid*4 + c] = v;
            xl[4*c+0] = v.x; xl[4*c+1] = v.y; xl[4*c+2] = v.z; xl[4*c+3] = v.w;
        }
    }
    if (tid < 8) ((float4*)s)[1024 + tid] = make_float4(0.f, 0.f, 0.f, 0.f); // zero pad

    // edge stashes (raw values) for autocorr boundary terms
    if (tid == 0) {
        for (int k = 0; k < 16; k++) red[232 + k] = xl[k];
    }
    if (tid == 1) {
        for (int k = 0; k < 8;  k++) red[248 + k] = xl[k];
    }
    if (tid == 254) {
        for (int k = 0; k < 8;  k++) red[256 + k] = xl[8 + k];
    }
    if (tid == 255) {
        for (int k = 0; k < 16; k++) red[264 + k] = xl[k];
    }

    float acc[9];   // s1 s2 s3 s4 R1 R3 R6 R12 R24 (raw sums)
    #pragma unroll
    for (int q = 0; q < 9; q++) acc[q] = 0.f;
    #pragma unroll
    for (int i = 0; i < 16; i++) {
        float v = xl[i], v2 = v*v;
        acc[0] += v; acc[1] += v2; acc[2] += v2*v; acc[3] += v2*v2;
        #pragma unroll
        for (int q = 0; q < 5; q++) {
            int j = i + lags[q];
            if (j < 16) acc[4+q] += v * xl[j];
        }
    }
    __syncthreads();   // sync 1: smem series complete (incl. zero pad)

    // cross-boundary lag products via warp shuffles (tail = next threads' xl);
    // lanes 30/31 fall back to smem (cross-warp; identical values, zero-pad at end)
    {
        const bool fixA = (lane == 31);   // shfl(+1) crosses warp
        const bool fixB = (lane >= 30);   // shfl(+2) crosses warp
        #pragma unroll
        for (int c2 = 0; c2 < 6; ++c2) {
            float tl4[4];
            #pragma unroll
            for (int kk = 0; kk < 4; kk++) {
                if (c2 < 4) tl4[kk] = __shfl_down_sync(~0u, xl[4*c2 + kk], 1);
                else        tl4[kk] = __shfl_down_sync(~0u, xl[4*(c2-4) + kk], 2);
            }
            if ((c2 < 4) ? fixA : fixB) {
                float4 v = *(const float4*)(s + tid*16 + 16 + 4*c2);
                tl4[0] = v.x; tl4[1] = v.y; tl4[2] = v.z; tl4[3] = v.w;
            }
            #pragma unroll
            for (int q = 0; q < 5; q++) {
                int l = lags[q];
                #pragma unroll
                for (int kk = 0; kk < 4; kk++) {
                    int k = 4*c2 + kk;
                    int i = 16 + k - l;
                    if (k < l && i >= 0) acc[4+q] += xl[i] * tl4[kk];
                }
            }
        }
    }
    // warp-reduce 9 raw sums -> red partials (finalized by tid0 at the end)
    #pragma unroll
    for (int q = 0; q < 9; q++) {
        float v = acc[q];
        #pragma unroll
        for (int o = 16; o > 0; o >>= 1) v += __shfl_down_sync(~0u, v, o);
        if (lane == 0) red[q*8 + warp] = v;
    }

    // ---- FFT group 0: radix-4 (S=2048), read z natural -> write ys swizzled.
    //      Different buffers: no WAR barrier needed between read and write. ----
    float2* z = (float2*)s;
    float2 xa[4], xb[4];
    #pragma unroll
    for (int j = 0; j < 4; j++) { xa[j] = z[tid + 512*j]; xb[j] = z[tid + 256 + 512*j]; }
    bfy4(xa, g_tw[tid],       g_tw[2*tid]);
    bfy4(xb, g_tw[tid + 256], g_tw[2*tid + 512]);
    #pragma unroll
    for (int j = 0; j < 4; j++) {
        ys[FZ(tid + 512*j)]       = xa[j];
        ys[FZ(tid + 256 + 512*j)] = xb[j];
    }
    __syncthreads();   // sync 2: g0 output ready in ys

    float2 zx[8];
    // ---- group 1: radix-8, S=512, q=64 (reads ys, writes z) ----
    {
        int o = tid & 63, base = (tid >> 6) * 512 + o;
        #pragma unroll
        for (int j = 0; j < 8; j++) zx[j] = ys[FZ(base + 64*j)];
        bfy8(zx, g_tw[4*o], g_tw[8*o], g_tw[16*o]);
        #pragma unroll
        for (int j = 0; j < 8; j++) z[FZ(base + 64*j)] = zx[j];
    }
    __syncthreads();   // sync 3
    // ---- group 2: radix-8, S=64, q=8 (in-place per-thread) ----
    {
        int o = tid & 7, base = (tid >> 3) * 64 + o;
        #pragma unroll
        for (int j = 0; j < 8; j++) zx[j] = z[FZ(base + 8*j)];
        bfy8(zx, g_tw[32*o], g_tw[64*o], g_tw[128*o]);
        #pragma unroll
        for (int j = 0; j < 8; j++) z[FZ(base + 8*j)] = zx[j];
    }
    __syncthreads();   // sync 4
    // ---- group 3: radix-8, S=8, q=1 (unit twiddles), fused de-reversal:
    //      outputs go straight to natural-order interleaved ys ----
    {
        int base = tid * 8;
        const float2 one = make_float2(1.f, 0.f);
        #pragma unroll
        for (int j = 0; j < 8; j++) zx[j] = z[FZ(base + j)];
        bfy8(zx, one, one, one);
        #pragma unroll
        for (int j = 0; j < 8; j++) {
            int k = __brev((unsigned)(base + j)) >> 21;   // natural bin
            ys[YA(k)] = zx[j];
        }
    }
    __syncthreads();   // sync 5: ys = natural spectrum

    // ---- unpack amplitudes via conjugate-pair symmetry, packed candidates ----
    u64 pk[9];
    float Ssum = 0.f, Smax = 0.f;
    #pragma unroll
    for (int c = 0; c < 4; ++c) {
        int k = 1 + tid + 256*c;          // 1..1024
        int m = 2048 - k;                 // 1024..2047
        float2 Zk = ys[YA(k)];
        float2 Zm = ys[YA(m)];
        float er  = 0.5f * (Zk.x + Zm.x);
        float ei  = 0.5f * (Zk.y - Zm.y);
        float orr = 0.5f * (Zk.y + Zm.y);
        float oi  = -0.5f * (Zk.x - Zm.x);
        float2 w = g_rot[k];
        float pr = w.x*orr - w.y*oi;
        float pi = w.x*oi  + w.y*orr;
        float xr = er + pr, xi2 = ei + pi;
        float ampk = sqrtf(xr*xr + xi2*xi2);
        float qr = er - pr, qi = ei - pi;
        float ampm = sqrtf(qr*qr + qi*qi);
        pk[c] = packcand(ampk, k);
        Ssum += ampk; Smax = fmaxf(Smax, ampk);
        if (k == 1024) { pk[4+c] = 0ull; }   // self-pair duplicate
        else {
            pk[4+c] = packcand(ampm, m);
            Ssum += ampm; Smax = fmaxf(Smax, ampm);
        }
    }
    pk[8] = 0ull;

    u64 c0 = 0ull, cN = 0ull;
    if (tid == 0) {
        float2 Z0 = ys[0];                // YA(0)==0
        float a0 = fabsf(Z0.x + Z0.y);    // bin 0
        float aN = fabsf(Z0.x - Z0.y);    // bin 2048
        c0 = packcand(a0, 0); cN = packcand(aN, 2048);
        Ssum += a0 + aN;
        Smax = fmaxf(Smax, fmaxf(a0, aN));
    }

    // sort pk[0..7] descending (packed order = value desc, key asc), Batcher
    #define CE(i,j) { if (pk[i] < pk[j]) { u64 t=pk[i]; pk[i]=pk[j]; pk[j]=t; } }
    CE(0,1) CE(2,3) CE(4,5) CE(6,7)
    CE(0,2) CE(1,3) CE(4,6) CE(5,7)
    CE(1,2) CE(5,6)
    CE(0,4) CE(1,5) CE(2,6) CE(3,7)
    CE(2,4) CE(3,5)
    CE(1,2) CE(3,4) CE(5,6)
    // tid0: insert bins 0 and 2048 (insert-with-drop keeps thread top-9)
    if (tid == 0) {
        if (c0 > pk[8]) pk[8] = c0;
        CE(7,8) CE(6,7) CE(5,6) CE(4,5) CE(3,4) CE(2,3) CE(1,2) CE(0,1)
        if (cN > pk[8]) pk[8] = cN;
        CE(7,8) CE(6,7) CE(5,6) CE(4,5) CE(3,4) CE(2,3) CE(1,2) CE(0,1)
    } else {
        CE(7,8) CE(6,7) CE(5,6) CE(4,5) CE(3,4) CE(2,3) CE(1,2) CE(0,1)
    }
    #undef CE

    // amp sum/max warp partials
    {
        float sv = Ssum, mv = Smax;
        #pragma unroll
        for (int o = 16; o > 0; o >>= 1) {
            sv += __shfl_down_sync(~0u, sv, o);
            mv = fmaxf(mv, __shfl_down_sync(~0u, mv, o));
        }
        if (lane == 0) { red[72 + warp] = sv; red[80 + warp] = mv; }
    }

    // ---- Phase A: warp-local tournament, register shift-queue (no smem lists) ----
    {
        #pragma unroll
        for (int r = 0; r < 9; ++r) {
            u64 h = pk[0];
            u64 b = h;
            #pragma unroll
            for (int o = 16; o > 0; o >>= 1) {
                u64 ob = __shfl_xor_sync(~0u, b, o);
                if (ob > b) b = ob;
            }
            if (h == b && h != 0ull) {      // this lane's head won: pop it
                #pragma unroll
                for (int qq = 0; qq < 8; qq++) pk[qq] = pk[qq+1];
                pk[8] = 0ull;
            }
            if (lane == 0) wl[warp*9 + r] = b;
        }
    }
    __syncthreads();   // sync 6: warp winners + amp partials visible

    // ---- Phase B: warp 0 merges 8 warp lists (register shift-queue) ----
    if (warp == 0) {
        u64 q[9];
        #pragma unroll
        for (int r = 0; r < 9; ++r) q[r] = (lane < 8) ? wl[lane*9 + r] : 0ull;
        #pragma unroll
        for (int r = 0; r < 9; ++r) {
            u64 h = q[0];
            u64 b = h;
            #pragma unroll
            for (int o = 4; o > 0; o >>= 1) {
                u64 ob = __shfl_xor_sync(~0u, b, o);
                if (ob > b) b = ob;
            }
            if (h == b && h != 0ull) {
                #pragma unroll
                for (int qq = 0; qq < 8; qq++) q[qq] = q[qq+1];
                q[8] = 0ull;
            }
            if (lane == 0) wl[72 + r] = b;
        }
    }

    // ---- epilogue (thread 0, same warp as Phase B writes) ----
    if (tid == 0) {
        float s1 = 0.f, s2 = 0.f, s3 = 0.f, s4 = 0.f, R[5] = {0,0,0,0,0};
        float S = 0.f, maxamp = 0.f;
        #pragma unroll
        for (int i = 0; i < 8; i++) {
            s1 += red[0*8+i]; s2 += red[1*8+i]; s3 += red[2*8+i]; s4 += red[3*8+i];
            R[0] += red[4*8+i]; R[1] += red[5*8+i]; R[2] += red[6*8+i];
            R[3] += red[7*8+i]; R[4] += red[8*8+i];
            S += red[72+i]; maxamp = fmaxf(maxamp, red[80+i]);
        }
        float topv[9]; int topi[9];
        #pragma unroll
        for (int r = 0; r < 9; ++r) {
            u64 w = wl[72 + r];
            topv[r] = __uint_as_float((unsigned)(w >> 32));
            topi[r] = 0x7fffffff ^ (int)(unsigned)w;
        }
        // edge prefix/suffix sums
        float H[25], T[25];
        H[0] = 0.f; T[0] = 0.f;
        #pragma unroll
        for (int k = 0; k < 24; k++) {
            H[k+1] = H[k] + red[232 + k];
            T[k+1] = T[k] + red[279 - k];
        }

        const float m  = s1 * (1.0f / L_);
        const float d2 = s2 - (float)L_ * m * m;
        const float d3 = s3 - 3.f*m*s2 + 2.f*(float)L_*m*m*m;
        const float d4 = s4 - 4.f*m*s3 + 6.f*m*m*s2 - 3.f*(float)L_*m*m*m*m;

        const float var  = d2 / (float)(L_ - 1);
        const float stdv = sqrtf(var);
        const float se   = stdv + 1e-8f;
        const float se2  = se * se;
        const float skew = (d3 / (float)L_) / (se * se2 + 1e-8f);
        const float kurt = (d4 / (float)L_) / (se2 * se2 + 1e-8f) - 3.0f;

        const float total = S / (float)FBINS + 1e-8f;
        float lvlsum[3] = { topv[0]+topv[1]+topv[2]+topv[3]+topv[4],
                            topv[5]+topv[6], topv[7] };
        float g[3]; float prefix = 0.f;
        #pragma unroll
        for (int l = 0; l < 3; l++) {
            float rr = ((S - prefix) / (float)FBINS) / total;
            float lr = 0.25f * (float)(l + 1);
            float o = b2v[0];
            #pragma unroll
            for (int j = 0; j < 8; j++) {
                float h = rr * w1[j] + lr * w1[8 + j] + b1v[j];
                h = 0.5f * h * (1.0f + erff(h * 0.70710678118654752f));
                o += h * w2[j];
            }
            g[l] = 1.0f / (1.0f + expf(-o));
            prefix += lvlsum[l];
        }
        const float r1 = g[0], r2 = g[0]*g[1], r3 = g[0]*g[1]*g[2];
        const float rf[9] = {1.f,1.f,1.f,1.f,1.f, r1, r1, r2, r3};
        float cv[9]; int ci[9];
        #pragma unroll
        for (int i = 0; i < 9; i++) { cv[i] = topv[i]*rf[i]; ci[i] = topi[i]; }
        for (int i = 1; i < 9; i++) {           // value desc, index asc on ties
            float v = cv[i]; int id = ci[i]; int j = i - 1;
            while (j >= 0 && (cv[j] < v || (cv[j] == v && ci[j] > id))) {
                cv[j+1] = cv[j]; ci[j+1] = ci[j]; j--;
            }
            cv[j+1] = v; ci[j+1] = id;
        }

        const float invden = 1.0f / (maxamp + 2e-8f);
        float* op = out + (size_t)blockIdx.x * 19;
        op[0] = m; op[1] = stdv; op[2] = skew; op[3] = kurt;
        #pragma unroll
        for (int i = 0; i < 5; i++) {
            op[4 + i] = (float)ci[i] * (1.0f / (float)L_);
            op[9 + i] = cv[i] * invden;
        }
        const int lags2[5] = {1, 3, 6, 12, 24};
        #pragma unroll
        for (int q = 0; q < 5; q++) {
            int l = lags2[q];
            float acsum = R[q] - m * ((s1 - T[l]) + (s1 - H[l])) + (float)(L_ - l) * m * m;
            op[14 + q] = (acsum / (float)(L_ - l)) / se2;
        }
    }
}

// ---------------------------------------------------------------------------
extern "C" void kernel_launch(void* const* d_in, const int* in_sizes, int n_in,
                              void* d_out, int out_size) {
    const float* x  = (const float*)d_in[0];
    const float* w1 = (const float*)d_in[1];
    const float* b1 = (const float*)d_in[2];
    const float* w2 = (const float*)d_in[3];
    const float* b2 = (const float*)d_in[4];
    float* out = (float*)d_out;

    dim3 tb(32, 8);
    dim3 tg(L_ / 32, N_ / 32, B_);
    transpose_kernel<<<tg, tb>>>(x);

    feat_kernel<<<NSERIES, NT>>>(w1, b1, w2, b2, out);
}

// round 13
// speedup vs baseline: 1.1691x; 1.0600x over previous
#include <cuda_runtime.h>
#include <math.h>

#define B_ 32
#define L_ 4096
#define N_ 256
#define NF 2048          // packed complex FFT size (L/2)
#define FBINS 2049       // rfft bins
#define NT 256
#define NSERIES (B_*N_)

typedef unsigned long long u64;

__device__ float  g_xt[(size_t)B_*N_*L_];   // (B,N,L) transposed input
__device__ float2 g_tw[NF/2];               // exp(-2*pi*i*j/2048)
__device__ float2 g_rot[NF];                // exp(-pi*i*k/2048)
// packed per-stage twiddle tables (consecutive / broadcast loads)
__device__ float2 g_t0b[512];               // tw(2i)
__device__ float2 g_t1a[64], g_t1b[64], g_t1c[64];   // tw(4o), tw(8o), tw(16o)
__device__ float2 g_t2a[8],  g_t2b[8],  g_t2c[8];    // tw(32o), tw(64o), tw(128o)

// XOR swizzle on float2 indices: conflict-free smem FFT exchanges
#define FZ(a) ((a) ^ (((a) >> 3) & 0xF))
// padded natural-order spectrum index
#define YA(k) ((k) + ((k) >> 3))
// float4-level XOR swizzle for the series buffer (phase-1 store / g0 read)
#define S4(a) ((a) ^ (((a) >> 3) & 7))

// packed candidate: value desc, key asc in ONE u64 compare (amps >= 0)
__device__ __forceinline__ u64 packcand(float v, int k) {
    return ((u64)__float_as_uint(v) << 32) | (unsigned)(0x7fffffff ^ k);
}

__device__ __forceinline__ float2 cmul(float2 a, float2 b) {
    return make_float2(a.x*b.x - a.y*b.y, a.x*b.y + a.y*b.x);
}
__device__ __forceinline__ float2 cadd(float2 a, float2 b) { return make_float2(a.x+b.x, a.y+b.y); }
__device__ __forceinline__ float2 csub(float2 a, float2 b) { return make_float2(a.x-b.x, a.y-b.y); }
__device__ __forceinline__ float2 cnegi(float2 a) { return make_float2(a.y, -a.x); }  // a * (-i)

// ---------------------------------------------------------------------------
// Tiled transpose x (B,L,N) -> g_xt (B,N,L); block (0,0,0) also fills twiddle tables.
__global__ void transpose_kernel(const float* __restrict__ x) {
    __shared__ float tile[32][33];
    int b  = blockIdx.z;
    int l0 = blockIdx.x << 5;
    int n0 = blockIdx.y << 5;
    int tx = threadIdx.x, ty = threadIdx.y;   // (32, 8)
    if (blockIdx.x == 0 && blockIdx.y == 0 && blockIdx.z == 0) {
        int tid = ty * 32 + tx;
        for (int i = tid; i < NF/2; i += 256) {
            float ang = -6.2831853071795864769f * (float)i / (float)NF;
            float sn, cs; sincosf(ang, &sn, &cs);
            g_tw[i] = make_float2(cs, sn);
        }
        for (int i = tid; i < NF; i += 256) {
            float ang = -3.1415926535897932385f * (float)i / (float)NF;
            float sn, cs; sincosf(ang, &sn, &cs);
            g_rot[i] = make_float2(cs, sn);
        }
        for (int i = tid; i < 512; i += 256) {
            float ang = -6.2831853071795864769f * (float)(2*i) / (float)NF;
            float sn, cs; sincosf(ang, &sn, &cs);
            g_t0b[i] = make_float2(cs, sn);
        }
        if (tid < 64) {
            float a1 = -6.2831853071795864769f * (float)(4*tid)  / (float)NF;
            float a2 = -6.2831853071795864769f * (float)(8*tid)  / (float)NF;
            float a3 = -6.2831853071795864769f * (float)(16*tid) / (float)NF;
            float sn, cs;
            sincosf(a1, &sn, &cs); g_t1a[tid] = make_float2(cs, sn);
            sincosf(a2, &sn, &cs); g_t1b[tid] = make_float2(cs, sn);
            sincosf(a3, &sn, &cs); g_t1c[tid] = make_float2(cs, sn);
        }
        if (tid < 8) {
            float a1 = -6.2831853071795864769f * (float)(32*tid)  / (float)NF;
            float a2 = -6.2831853071795864769f * (float)(64*tid)  / (float)NF;
            float a3 = -6.2831853071795864769f * (float)(128*tid) / (float)NF;
            float sn, cs;
            sincosf(a1, &sn, &cs); g_t2a[tid] = make_float2(cs, sn);
            sincosf(a2, &sn, &cs); g_t2b[tid] = make_float2(cs, sn);
            sincosf(a3, &sn, &cs); g_t2c[tid] = make_float2(cs, sn);
        }
    }
    #pragma unroll
    for (int i = 0; i < 32; i += 8)
        tile[ty + i][tx] = x[((size_t)b * L_ + (l0 + ty + i)) * N_ + n0 + tx];
    __syncthreads();
    #pragma unroll
    for (int i = 0; i < 32; i += 8)
        g_xt[((size_t)b * N_ + (n0 + ty + i)) * L_ + l0 + tx] = tile[tx][ty + i];
}

// ---------------------------------------------------------------------------
// radix-4 DIF butterfly (in-place digit placement)
__device__ __forceinline__ void bfy4(float2* x, float2 wa, float2 wb) {
    float2 wami = cnegi(wa);
    float2 t0 = cadd(x[0], x[2]), u0 = cmul(csub(x[0], x[2]), wa);
    float2 t1 = cadd(x[1], x[3]), u1 = cmul(csub(x[1], x[3]), wami);
    x[0] = cadd(t0, t1); x[1] = cmul(csub(t0, t1), wb);
    x[2] = cadd(u0, u1); x[3] = cmul(csub(u0, u1), wb);
}

// radix-8 DIF butterfly = 3 in-place radix-2 stages on 8 register values.
__device__ __forceinline__ void bfy8(float2* x, float2 wa, float2 wb, float2 wc) {
    const float R2 = 0.70710678118654752440f;
    float2 wa1 = cmul(wa, make_float2(R2, -R2));
    float2 wa2 = cnegi(wa);
    float2 wa3 = cnegi(wa1);
    float2 wbi = cnegi(wb);
    float2 d;
    d = csub(x[0], x[4]); x[0] = cadd(x[0], x[4]); x[4] = cmul(d, wa);
    d = csub(x[1], x[5]); x[1] = cadd(x[1], x[5]); x[5] = cmul(d, wa1);
    d = csub(x[2], x[6]); x[2] = cadd(x[2], x[6]); x[6] = cmul(d, wa2);
    d = csub(x[3], x[7]); x[3] = cadd(x[3], x[7]); x[7] = cmul(d, wa3);
    d = csub(x[0], x[2]); x[0] = cadd(x[0], x[2]); x[2] = cmul(d, wb);
    d = csub(x[1], x[3]); x[1] = cadd(x[1], x[3]); x[3] = cmul(d, wbi);
    d = csub(x[4], x[6]); x[4] = cadd(x[4], x[6]); x[6] = cmul(d, wb);
    d = csub(x[5], x[7]); x[5] = cadd(x[5], x[7]); x[7] = cmul(d, wbi);
    d = csub(x[0], x[1]); x[0] = cadd(x[0], x[1]); x[1] = cmul(d, wc);
    d = csub(x[2], x[3]); x[2] = cadd(x[2], x[3]); x[3] = cmul(d, wc);
    d = csub(x[4], x[5]); x[4] = cadd(x[4], x[5]); x[5] = cmul(d, wc);
    d = csub(x[6], x[7]); x[6] = cadd(x[6], x[7]); x[7] = cmul(d, wc);
}

// ---------------------------------------------------------------------------
// One CTA per (b,n) series.
__global__ __launch_bounds__(NT, 4) void feat_kernel(
    const float* __restrict__ w1, const float* __restrict__ b1v,
    const float* __restrict__ w2, const float* __restrict__ b2v,
    float* __restrict__ out)
{
    __shared__ __align__(16) float s[4608];  // series (S4-swizzled) / FFT z[] (FZ-swizzled)
    __shared__ float2 ys[2304];  // g0 ping-pong scratch; later natural-order spectrum (YA padding)
    __shared__ u64   wl[81];     // 8 warp top-9 lists + global top-9
    __shared__ float red[304];
    // red: [0..71] 9x8 moment partials | [72..79] ampsum | [80..87] ampmax
    //      [232..255] head24 | [256..279] tail24

    const int tid  = threadIdx.x;
    const int lane = tid & 31, warp = tid >> 5;
    const int lags[5] = {1, 3, 6, 12, 24};

    // ---- phase 1: contiguous load, S4-swizzled STS (conflict-free), raw moments ----
    float xl[16];
    {
        const float4* __restrict__ src4 =
            (const float4*)(g_xt + (size_t)blockIdx.x * L_ + tid * 16);
        float4* sm4 = (float4*)s;
        #pragma unroll
        for (int c = 0; c < 4; ++c) {
            float4 v = src4[c];
            sm4[S4(tid*4 + c)] = v;
            xl[4*c+0] = v.x; xl[4*c+1] = v.y; xl[4*c+2] = v.z; xl[4*c+3] = v.w;
        }
    }
    if (tid < 8) ((float4*)s)[1024 + tid] = make_float4(0.f, 0.f, 0.f, 0.f); // pad (S4 = identity here)

    // edge stashes (raw values) for autocorr boundary terms
    if (tid == 0) {
        for (int k = 0; k < 16; k++) red[232 + k] = xl[k];
    }
    if (tid == 1) {
        for (int k = 0; k < 8;  k++) red[248 + k] = xl[k];
    }
    if (tid == 254) {
        for (int k = 0; k < 8;  k++) red[256 + k] = xl[8 + k];
    }
    if (tid == 255) {
        for (int k = 0; k < 16; k++) red[264 + k] = xl[k];
    }

    float acc[9];   // s1 s2 s3 s4 R1 R3 R6 R12 R24 (raw sums)
    #pragma unroll
    for (int q = 0; q < 9; q++) acc[q] = 0.f;
    #pragma unroll
    for (int i = 0; i < 16; i++) {
        float v = xl[i], v2 = v*v;
        acc[0] += v; acc[1] += v2; acc[2] += v2*v; acc[3] += v2*v2;
        #pragma unroll
        for (int q = 0; q < 5; q++) {
            int j = i + lags[q];
            if (j < 16) acc[4+q] += v * xl[j];
        }
    }
    __syncthreads();   // sync 1: smem series complete (incl. zero pad)

    // cross-boundary lag products via warp shuffles (tail = next threads' xl);
    // lanes 30/31 fall back to smem (S4-swizzled; identical values, zero-pad at end)
    {
        const bool fixA = (lane == 31);   // shfl(+1) crosses warp
        const bool fixB = (lane >= 30);   // shfl(+2) crosses warp
        #pragma unroll
        for (int c2 = 0; c2 < 6; ++c2) {
            float tl4[4];
            #pragma unroll
            for (int kk = 0; kk < 4; kk++) {
                if (c2 < 4) tl4[kk] = __shfl_down_sync(~0u, xl[4*c2 + kk], 1);
                else        tl4[kk] = __shfl_down_sync(~0u, xl[4*(c2-4) + kk], 2);
            }
            if ((c2 < 4) ? fixA : fixB) {
                float4 v = ((const float4*)s)[S4(tid*4 + 4 + c2)];
                tl4[0] = v.x; tl4[1] = v.y; tl4[2] = v.z; tl4[3] = v.w;
            }
            #pragma unroll
            for (int q = 0; q < 5; q++) {
                int l = lags[q];
                #pragma unroll
                for (int kk = 0; kk < 4; kk++) {
                    int k = 4*c2 + kk;
                    int i = 16 + k - l;
                    if (k < l && i >= 0) acc[4+q] += xl[i] * tl4[kk];
                }
            }
        }
    }
    // warp-reduce 9 raw sums -> red partials (finalized by tid0 at the end)
    #pragma unroll
    for (int q = 0; q < 9; q++) {
        float v = acc[q];
        #pragma unroll
        for (int o = 16; o > 0; o >>= 1) v += __shfl_down_sync(~0u, v, o);
        if (lane == 0) red[q*8 + warp] = v;
    }

    // ---- FFT group 0: radix-4 (S=2048), read s (S4 layout) -> write ys swizzled. ----
    float2* z = (float2*)s;
    const float2* s2 = (const float2*)s;
    float2 xa[4], xb[4];
    #pragma unroll
    for (int j = 0; j < 4; j++) {
        int va = tid + 512*j, vb = tid + 256 + 512*j;
        xa[j] = s2[(S4(va >> 1) << 1) | (va & 1)];
        xb[j] = s2[(S4(vb >> 1) << 1) | (vb & 1)];
    }
    bfy4(xa, g_tw[tid],       g_t0b[tid]);
    bfy4(xb, g_tw[tid + 256], g_t0b[tid + 256]);
    #pragma unroll
    for (int j = 0; j < 4; j++) {
        ys[FZ(tid + 512*j)]       = xa[j];
        ys[FZ(tid + 256 + 512*j)] = xb[j];
    }
    __syncthreads();   // sync 2: g0 output ready in ys

    float2 zx[8];
    // ---- group 1: radix-8, S=512, q=64 (reads ys, writes z; packed twiddles) ----
    {
        int o = tid & 63, base = (tid >> 6) * 512 + o;
        #pragma unroll
        for (int j = 0; j < 8; j++) zx[j] = ys[FZ(base + 64*j)];
        bfy8(zx, g_t1a[o], g_t1b[o], g_t1c[o]);
        #pragma unroll
        for (int j = 0; j < 8; j++) z[FZ(base + 64*j)] = zx[j];
    }
    __syncthreads();   // sync 3
    // ---- group 2: radix-8, S=64, q=8 (in-place per-thread; packed twiddles) ----
    {
        int o = tid & 7, base = (tid >> 3) * 64 + o;
        #pragma unroll
        for (int j = 0; j < 8; j++) zx[j] = z[FZ(base + 8*j)];
        bfy8(zx, g_t2a[o], g_t2b[o], g_t2c[o]);
        #pragma unroll
        for (int j = 0; j < 8; j++) z[FZ(base + 8*j)] = zx[j];
    }
    __syncthreads();   // sync 4
    // ---- group 3: radix-8, S=8, q=1 (unit twiddles), fused de-reversal ----
    {
        int base = tid * 8;
        const float2 one = make_float2(1.f, 0.f);
        #pragma unroll
        for (int j = 0; j < 8; j++) zx[j] = z[FZ(base + j)];
        bfy8(zx, one, one, one);
        #pragma unroll
        for (int j = 0; j < 8; j++) {
            int k = __brev((unsigned)(base + j)) >> 21;   // natural bin
            ys[YA(k)] = zx[j];
        }
    }
    __syncthreads();   // sync 5: ys = natural spectrum

    // ---- unpack amplitudes via conjugate-pair symmetry, packed candidates ----
    u64 pk[9];
    float Ssum = 0.f, Smax = 0.f;
    #pragma unroll
    for (int c = 0; c < 4; ++c) {
        int k = 1 + tid + 256*c;          // 1..1024
        int m = 2048 - k;                 // 1024..2047
        float2 Zk = ys[YA(k)];
        float2 Zm = ys[YA(m)];
        float er  = 0.5f * (Zk.x + Zm.x);
        float ei  = 0.5f * (Zk.y - Zm.y);
        float orr = 0.5f * (Zk.y + Zm.y);
        float oi  = -0.5f * (Zk.x - Zm.x);
        float2 w = g_rot[k];
        float pr = w.x*orr - w.y*oi;
        float pi = w.x*oi  + w.y*orr;
        float xr = er + pr, xi2 = ei + pi;
        float ampk = sqrtf(xr*xr + xi2*xi2);
        float qr = er - pr, qi = ei - pi;
        float ampm = sqrtf(qr*qr + qi*qi);
        pk[c] = packcand(ampk, k);
        Ssum += ampk; Smax = fmaxf(Smax, ampk);
        if (k == 1024) { pk[4+c] = 0ull; }   // self-pair duplicate
        else {
            pk[4+c] = packcand(ampm, m);
            Ssum += ampm; Smax = fmaxf(Smax, ampm);
        }
    }
    pk[8] = 0ull;

    u64 c0 = 0ull, cN = 0ull;
    if (tid == 0) {
        float2 Z0 = ys[0];                // YA(0)==0
        float a0 = fabsf(Z0.x + Z0.y);    // bin 0
        float aN = fabsf(Z0.x - Z0.y);    // bin 2048
        c0 = packcand(a0, 0); cN = packcand(aN, 2048);
        Ssum += a0 + aN;
        Smax = fmaxf(Smax, fmaxf(a0, aN));
    }

    // sort pk[0..7] descending (packed order = value desc, key asc), Batcher
    #define CE(i,j) { if (pk[i] < pk[j]) { u64 t=pk[i]; pk[i]=pk[j]; pk[j]=t; } }
    CE(0,1) CE(2,3) CE(4,5) CE(6,7)
    CE(0,2) CE(1,3) CE(4,6) CE(5,7)
    CE(1,2) CE(5,6)
    CE(0,4) CE(1,5) CE(2,6) CE(3,7)
    CE(2,4) CE(3,5)
    CE(1,2) CE(3,4) CE(5,6)
    // tid0: insert bins 0 and 2048 (insert-with-drop keeps thread top-9)
    if (tid == 0) {
        if (c0 > pk[8]) pk[8] = c0;
        CE(7,8) CE(6,7) CE(5,6) CE(4,5) CE(3,4) CE(2,3) CE(1,2) CE(0,1)
        if (cN > pk[8]) pk[8] = cN;
        CE(7,8) CE(6,7) CE(5,6) CE(4,5) CE(3,4) CE(2,3) CE(1,2) CE(0,1)
    } else {
        CE(7,8) CE(6,7) CE(5,6) CE(4,5) CE(3,4) CE(2,3) CE(1,2) CE(0,1)
    }
    #undef CE

    // amp sum/max warp partials
    {
        float sv = Ssum, mv = Smax;
        #pragma unroll
        for (int o = 16; o > 0; o >>= 1) {
            sv += __shfl_down_sync(~0u, sv, o);
            mv = fmaxf(mv, __shfl_down_sync(~0u, mv, o));
        }
        if (lane == 0) { red[72 + warp] = sv; red[80 + warp] = mv; }
    }

    // ---- Phase A: warp-local tournament, register shift-queue (no smem lists) ----
    {
        #pragma unroll
        for (int r = 0; r < 9; ++r) {
            u64 h = pk[0];
            u64 b = h;
            #pragma unroll
            for (int o = 16; o > 0; o >>= 1) {
                u64 ob = __shfl_xor_sync(~0u, b, o);
                if (ob > b) b = ob;
            }
            if (h == b && h != 0ull) {      // this lane's head won: pop it
                #pragma unroll
                for (int qq = 0; qq < 8; qq++) pk[qq] = pk[qq+1];
                pk[8] = 0ull;
            }
            if (lane == 0) wl[warp*9 + r] = b;
        }
    }
    __syncthreads();   // sync 6: warp winners + amp partials visible

    // ---- Phase B: warp 0 merges 8 warp lists (register shift-queue) ----
    if (warp == 0) {
        u64 q[9];
        #pragma unroll
        for (int r = 0; r < 9; ++r) q[r] = (lane < 8) ? wl[lane*9 + r] : 0ull;
        #pragma unroll
        for (int r = 0; r < 9; ++r) {
            u64 h = q[0];
            u64 b = h;
            #pragma unroll
            for (int o = 4; o > 0; o >>= 1) {
                u64 ob = __shfl_xor_sync(~0u, b, o);
                if (ob > b) b = ob;
            }
            if (h == b && h != 0ull) {
                #pragma unroll
                for (int qq = 0; qq < 8; qq++) q[qq] = q[qq+1];
                q[8] = 0ull;
            }
            if (lane == 0) wl[72 + r] = b;
        }
    }

    // ---- epilogue (thread 0, same warp as Phase B writes) ----
    if (tid == 0) {
        float s1 = 0.f, s2a = 0.f, s3 = 0.f, s4 = 0.f, R[5] = {0,0,0,0,0};
        float S = 0.f, maxamp = 0.f;
        #pragma unroll
        for (int i = 0; i < 8; i++) {
            s1 += red[0*8+i]; s2a += red[1*8+i]; s3 += red[2*8+i]; s4 += red[3*8+i];
            R[0] += red[4*8+i]; R[1] += red[5*8+i]; R[2] += red[6*8+i];
            R[3] += red[7*8+i]; R[4] += red[8*8+i];
            S += red[72+i]; maxamp = fmaxf(maxamp, red[80+i]);
        }
        float topv[9]; int topi[9];
        #pragma unroll
        for (int r = 0; r < 9; ++r) {
            u64 w = wl[72 + r];
            topv[r] = __uint_as_float((unsigned)(w >> 32));
            topi[r] = 0x7fffffff ^ (int)(unsigned)w;
        }
        // edge prefix/suffix sums
        float H[25], T[25];
        H[0] = 0.f; T[0] = 0.f;
        #pragma unroll
        for (int k = 0; k < 24; k++) {
            H[k+1] = H[k] + red[232 + k];
            T[k+1] = T[k] + red[279 - k];
        }

        const float m  = s1 * (1.0f / L_);
        const float d2 = s2a - (float)L_ * m * m;
        const float d3 = s3 - 3.f*m*s2a + 2.f*(float)L_*m*m*m;
        const float d4 = s4 - 4.f*m*s3 + 6.f*m*m*s2a - 3.f*(float)L_*m*m*m*m;

        const float var  = d2 / (float)(L_ - 1);
        const float stdv = sqrtf(var);
        const float se   = stdv + 1e-8f;
        const float se2  = se * se;
        const float skew = (d3 / (float)L_) / (se * se2 + 1e-8f);
        const float kurt = (d4 / (float)L_) / (se2 * se2 + 1e-8f) - 3.0f;

        const float total = S / (float)FBINS + 1e-8f;
        float lvlsum[3] = { topv[0]+topv[1]+topv[2]+topv[3]+topv[4],
                            topv[5]+topv[6], topv[7] };
        float g[3]; float prefix = 0.f;
        #pragma unroll
        for (int l = 0; l < 3; l++) {
            float rr = ((S - prefix) / (float)FBINS) / total;
            float lr = 0.25f * (float)(l + 1);
            float o = b2v[0];
            #pragma unroll
            for (int j = 0; j < 8; j++) {
                float h = rr * w1[j] + lr * w1[8 + j] + b1v[j];
                h = 0.5f * h * (1.0f + erff(h * 0.70710678118654752f));
                o += h * w2[j];
            }
            g[l] = 1.0f / (1.0f + expf(-o));
            prefix += lvlsum[l];
        }
        const float r1 = g[0], r2 = g[0]*g[1], r3 = g[0]*g[1]*g[2];
        const float rf[9] = {1.f,1.f,1.f,1.f,1.f, r1, r1, r2, r3};
        float cv[9]; int ci[9];
        #pragma unroll
        for (int i = 0; i < 9; i++) { cv[i] = topv[i]*rf[i]; ci[i] = topi[i]; }
        for (int i = 1; i < 9; i++) {           // value desc, index asc on ties
            float v = cv[i]; int id = ci[i]; int j = i - 1;
            while (j >= 0 && (cv[j] < v || (cv[j] == v && ci[j] > id))) {
                cv[j+1] = cv[j]; ci[j+1] = ci[j]; j--;
            }
            cv[j+1] = v; ci[j+1] = id;
        }

        const float invden = 1.0f / (maxamp + 2e-8f);
        float* op = out + (size_t)blockIdx.x * 19;
        op[0] = m; op[1] = stdv; op[2] = skew; op[3] = kurt;
        #pragma unroll
        for (int i = 0; i < 5; i++) {
            op[4 + i] = (float)ci[i] * (1.0f / (float)L_);
            op[9 + i] = cv[i] * invden;
        }
        const int lags2[5] = {1, 3, 6, 12, 24};
        #pragma unroll
        for (int q = 0; q < 5; q++) {
            int l = lags2[q];
            float acsum = R[q] - m * ((s1 - T[l]) + (s1 - H[l])) + (float)(L_ - l) * m * m;
            op[14 + q] = (acsum / (float)(L_ - l)) / se2;
        }
    }
}

// ---------------------------------------------------------------------------
extern "C" void kernel_launch(void* const* d_in, const int* in_sizes, int n_in,
                              void* d_out, int out_size) {
    const float* x  = (const float*)d_in[0];
    const float* w1 = (const float*)d_in[1];
    const float* b1 = (const float*)d_in[2];
    const float* w2 = (const float*)d_in[3];
    const float* b2 = (const float*)d_in[4];
    float* out = (float*)d_out;

    dim3 tb(32, 8);
    dim3 tg(L_ / 32, N_ / 32, B_);
    transpose_kernel<<<tg, tb>>>(x);

    feat_kernel<<<NSERIES, NT>>>(w1, b1, w2, b2, out);
}

// round 15
// speedup vs baseline: 1.1759x; 1.0058x over previous
#include <cuda_runtime.h>
#include <math.h>

#define B_ 32
#define L_ 4096
#define N_ 256
#define NF 2048          // packed complex FFT size (L/2)
#define FBINS 2049       // rfft bins
#define NT 256
#define NSERIES (B_*N_)

typedef unsigned long long u64;

__device__ float  g_xt[(size_t)B_*N_*L_];   // (B,N,L) transposed input
__device__ float2 g_tw[NF/2];               // exp(-2*pi*i*j/2048)
__device__ float2 g_rot[NF];                // exp(-pi*i*k/2048)
// packed per-stage twiddle tables (consecutive / broadcast loads)
__device__ float2 g_t0b[512];               // tw(2i)
__device__ float2 g_t1a[64], g_t1b[64], g_t1c[64];   // tw(4o), tw(8o), tw(16o)
__device__ float2 g_t2a[8],  g_t2b[8],  g_t2c[8];    // tw(32o), tw(64o), tw(128o)

// XOR swizzle on float2 indices: conflict-free smem FFT exchanges
#define FZ(a) ((a) ^ (((a) >> 3) & 0xF))
// padded natural-order spectrum index
#define YA(k) ((k) + ((k) >> 3))
// float4-level XOR swizzle for the series buffer (phase-1 store / g0 read)
#define S4(a) ((a) ^ (((a) >> 3) & 7))

// packed candidate: value desc, key asc in ONE u64 compare (amps >= 0)
__device__ __forceinline__ u64 packcand(float v, int k) {
    return ((u64)__float_as_uint(v) << 32) | (unsigned)(0x7fffffff ^ k);
}

__device__ __forceinline__ float2 cmul(float2 a, float2 b) {
    return make_float2(a.x*b.x - a.y*b.y, a.x*b.y + a.y*b.x);
}
__device__ __forceinline__ float2 cadd(float2 a, float2 b) { return make_float2(a.x+b.x, a.y+b.y); }
__device__ __forceinline__ float2 csub(float2 a, float2 b) { return make_float2(a.x-b.x, a.y-b.y); }
__device__ __forceinline__ float2 cnegi(float2 a) { return make_float2(a.y, -a.x); }  // a * (-i)

// ---------------------------------------------------------------------------
// Vectorized tiled transpose x (B,L,N) -> g_xt (B,N,L).
// Block (8,32): LDG.128 along N, STG.128 along L; 33-pad tile (both smem
// phases verified conflict-free). Block (0,0,0) also fills twiddle tables.
__global__ void transpose_kernel(const float* __restrict__ x) {
    __shared__ float tile[32][33];   // [l][n]
    int b  = blockIdx.z;
    int l0 = blockIdx.x << 5;
    int n0 = blockIdx.y << 5;
    int tx = threadIdx.x, ty = threadIdx.y;   // (8, 32)
    if (blockIdx.x == 0 && blockIdx.y == 0 && blockIdx.z == 0) {
        int tid = ty * 8 + tx;
        for (int i = tid; i < NF/2; i += 256) {
            float ang = -6.2831853071795864769f * (float)i / (float)NF;
            float sn, cs; sincosf(ang, &sn, &cs);
            g_tw[i] = make_float2(cs, sn);
        }
        for (int i = tid; i < NF; i += 256) {
            float ang = -3.1415926535897932385f * (float)i / (float)NF;
            float sn, cs; sincosf(ang, &sn, &cs);
            g_rot[i] = make_float2(cs, sn);
        }
        for (int i = tid; i < 512; i += 256) {
            float ang = -6.2831853071795864769f * (float)(2*i) / (float)NF;
            float sn, cs; sincosf(ang, &sn, &cs);
            g_t0b[i] = make_float2(cs, sn);
        }
        if (tid < 64) {
            float a1 = -6.2831853071795864769f * (float)(4*tid)  / (float)NF;
            float a2 = -6.2831853071795864769f * (float)(8*tid)  / (float)NF;
            float a3 = -6.2831853071795864769f * (float)(16*tid) / (float)NF;
            float sn, cs;
            sincosf(a1, &sn, &cs); g_t1a[tid] = make_float2(cs, sn);
            sincosf(a2, &sn, &cs); g_t1b[tid] = make_float2(cs, sn);
            sincosf(a3, &sn, &cs); g_t1c[tid] = make_float2(cs, sn);
        }
        if (tid < 8) {
            float a1 = -6.2831853071795864769f * (float)(32*tid)  / (float)NF;
            float a2 = -6.2831853071795864769f * (float)(64*tid)  / (float)NF;
            float a3 = -6.2831853071795864769f * (float)(128*tid) / (float)NF;
            float sn, cs;
            sincosf(a1, &sn, &cs); g_t2a[tid] = make_float2(cs, sn);
            sincosf(a2, &sn, &cs); g_t2b[tid] = make_float2(cs, sn);
            sincosf(a3, &sn, &cs); g_t2c[tid] = make_float2(cs, sn);
        }
    }
    // load: one float4 along N per thread
    {
        float4 v = *(const float4*)(x + ((size_t)b * L_ + (l0 + ty)) * N_ + n0 + 4*tx);
        tile[ty][4*tx + 0] = v.x;
        tile[ty][4*tx + 1] = v.y;
        tile[ty][4*tx + 2] = v.z;
        tile[ty][4*tx + 3] = v.w;
    }
    __syncthreads();
    // store: one float4 along L per thread (gather 4 strided tile reads)
    {
        float4 v;
        v.x = tile[4*tx + 0][ty];
        v.y = tile[4*tx + 1][ty];
        v.z = tile[4*tx + 2][ty];
        v.w = tile[4*tx + 3][ty];
        *(float4*)(g_xt + ((size_t)b * N_ + (n0 + ty)) * L_ + l0 + 4*tx) = v;
    }
}

// ---------------------------------------------------------------------------
// radix-4 DIF butterfly (in-place digit placement)
__device__ __forceinline__ void bfy4(float2* x, float2 wa, float2 wb) {
    float2 wami = cnegi(wa);
    float2 t0 = cadd(x[0], x[2]), u0 = cmul(csub(x[0], x[2]), wa);
    float2 t1 = cadd(x[1], x[3]), u1 = cmul(csub(x[1], x[3]), wami);
    x[0] = cadd(t0, t1); x[1] = cmul(csub(t0, t1), wb);
    x[2] = cadd(u0, u1); x[3] = cmul(csub(u0, u1), wb);
}

// radix-8 DIF butterfly = 3 in-place radix-2 stages on 8 register values.
__device__ __forceinline__ void bfy8(float2* x, float2 wa, float2 wb, float2 wc) {
    const float R2 = 0.70710678118654752440f;
    float2 wa1 = cmul(wa, make_float2(R2, -R2));
    float2 wa2 = cnegi(wa);
    float2 wa3 = cnegi(wa1);
    float2 wbi = cnegi(wb);
    float2 d;
    d = csub(x[0], x[4]); x[0] = cadd(x[0], x[4]); x[4] = cmul(d, wa);
    d = csub(x[1], x[5]); x[1] = cadd(x[1], x[5]); x[5] = cmul(d, wa1);
    d = csub(x[2], x[6]); x[2] = cadd(x[2], x[6]); x[6] = cmul(d, wa2);
    d = csub(x[3], x[7]); x[3] = cadd(x[3], x[7]); x[7] = cmul(d, wa3);
    d = csub(x[0], x[2]); x[0] = cadd(x[0], x[2]); x[2] = cmul(d, wb);
    d = csub(x[1], x[3]); x[1] = cadd(x[1], x[3]); x[3] = cmul(d, wbi);
    d = csub(x[4], x[6]); x[4] = cadd(x[4], x[6]); x[6] = cmul(d, wb);
    d = csub(x[5], x[7]); x[5] = cadd(x[5], x[7]); x[7] = cmul(d, wbi);
    d = csub(x[0], x[1]); x[0] = cadd(x[0], x[1]); x[1] = cmul(d, wc);
    d = csub(x[2], x[3]); x[2] = cadd(x[2], x[3]); x[3] = cmul(d, wc);
    d = csub(x[4], x[5]); x[4] = cadd(x[4], x[5]); x[5] = cmul(d, wc);
    d = csub(x[6], x[7]); x[6] = cadd(x[6], x[7]); x[7] = cmul(d, wc);
}

// ---------------------------------------------------------------------------
// One CTA per (b,n) series.
__global__ __launch_bounds__(NT, 4) void feat_kernel(
    const float* __restrict__ w1, const float* __restrict__ b1v,
    const float* __restrict__ w2, const float* __restrict__ b2v,
    float* __restrict__ out)
{
    __shared__ __align__(16) float s[4608];  // series (S4-swizzled) / FFT z[] (FZ-swizzled)
    __shared__ float2 ys[2304];  // g0 ping-pong scratch; later natural-order spectrum (YA padding)
    __shared__ u64   wl[81];     // 8 warp top-9 lists + global top-9
    __shared__ float red[304];
    // red: [0..71] 9x8 moment partials | [72..79] ampsum | [80..87] ampmax
    //      [232..255] head24 | [256..279] tail24

    const int tid  = threadIdx.x;
    const int lane = tid & 31, warp = tid >> 5;
    const int lags[5] = {1, 3, 6, 12, 24};

    // ---- phase 1: contiguous load, S4-swizzled STS (conflict-free), raw moments ----
    float xl[16];
    {
        const float4* __restrict__ src4 =
            (const float4*)(g_xt + (size_t)blockIdx.x * L_ + tid * 16);
        float4* sm4 = (float4*)s;
        #pragma unroll
        for (int c = 0; c < 4; ++c) {
            float4 v = src4[c];
            sm4[S4(tid*4 + c)] = v;
            xl[4*c+0] = v.x; xl[4*c+1] = v.y; xl[4*c+2] = v.z; xl[4*c+3] = v.w;
        }
    }
    if (tid < 8) ((float4*)s)[1024 + tid] = make_float4(0.f, 0.f, 0.f, 0.f); // pad (S4 = identity here)

    // edge stashes (raw values) for autocorr boundary terms
    if (tid == 0) {
        for (int k = 0; k < 16; k++) red[232 + k] = xl[k];
    }
    if (tid == 1) {
        for (int k = 0; k < 8;  k++) red[248 + k] = xl[k];
    }
    if (tid == 254) {
        for (int k = 0; k < 8;  k++) red[256 + k] = xl[8 + k];
    }
    if (tid == 255) {
        for (int k = 0; k < 16; k++) red[264 + k] = xl[k];
    }

    float acc[9];   // s1 s2 s3 s4 R1 R3 R6 R12 R24 (raw sums)
    #pragma unroll
    for (int q = 0; q < 9; q++) acc[q] = 0.f;
    #pragma unroll
    for (int i = 0; i < 16; i++) {
        float v = xl[i], v2 = v*v;
        acc[0] += v; acc[1] += v2; acc[2] += v2*v; acc[3] += v2*v2;
        #pragma unroll
        for (int q = 0; q < 5; q++) {
            int j = i + lags[q];
            if (j < 16) acc[4+q] += v * xl[j];
        }
    }
    __syncthreads();   // sync 1: smem series complete (incl. zero pad)

    // cross-boundary lag products via warp shuffles (tail = next threads' xl);
    // lanes 30/31 fall back to smem (S4-swizzled; identical values, zero-pad at end)
    {
        const bool fixA = (lane == 31);   // shfl(+1) crosses warp
        const bool fixB = (lane >= 30);   // shfl(+2) crosses warp
        #pragma unroll
        for (int c2 = 0; c2 < 6; ++c2) {
            float tl4[4];
            #pragma unroll
            for (int kk = 0; kk < 4; kk++) {
                if (c2 < 4) tl4[kk] = __shfl_down_sync(~0u, xl[4*c2 + kk], 1);
                else        tl4[kk] = __shfl_down_sync(~0u, xl[4*(c2-4) + kk], 2);
            }
            if ((c2 < 4) ? fixA : fixB) {
                float4 v = ((const float4*)s)[S4(tid*4 + 4 + c2)];
                tl4[0] = v.x; tl4[1] = v.y; tl4[2] = v.z; tl4[3] = v.w;
            }
            #pragma unroll
            for (int q = 0; q < 5; q++) {
                int l = lags[q];
                #pragma unroll
                for (int kk = 0; kk < 4; kk++) {
                    int k = 4*c2 + kk;
                    int i = 16 + k - l;
                    if (k < l && i >= 0) acc[4+q] += xl[i] * tl4[kk];
                }
            }
        }
    }
    // warp-reduce 9 raw sums -> red partials (finalized by tid0 at the end)
    #pragma unroll
    for (int q = 0; q < 9; q++) {
        float v = acc[q];
        #pragma unroll
        for (int o = 16; o > 0; o >>= 1) v += __shfl_down_sync(~0u, v, o);
        if (lane == 0) red[q*8 + warp] = v;
    }

    // ---- FFT group 0: radix-4 (S=2048), read s (S4 layout) -> write ys swizzled. ----
    float2* z = (float2*)s;
    const float2* s2 = (const float2*)s;
    float2 xa[4], xb[4];
    #pragma unroll
    for (int j = 0; j < 4; j++) {
        int va = tid + 512*j, vb = tid + 256 + 512*j;
        xa[j] = s2[(S4(va >> 1) << 1) | (va & 1)];
        xb[j] = s2[(S4(vb >> 1) << 1) | (vb & 1)];
    }
    bfy4(xa, g_tw[tid],       g_t0b[tid]);
    bfy4(xb, g_tw[tid + 256], g_t0b[tid + 256]);
    #pragma unroll
    for (int j = 0; j < 4; j++) {
        ys[FZ(tid + 512*j)]       = xa[j];
        ys[FZ(tid + 256 + 512*j)] = xb[j];
    }
    __syncthreads();   // sync 2: g0 output ready in ys

    float2 zx[8];
    // ---- group 1: radix-8, S=512, q=64 (reads ys, writes z; packed twiddles) ----
    {
        int o = tid & 63, base = (tid >> 6) * 512 + o;
        #pragma unroll
        for (int j = 0; j < 8; j++) zx[j] = ys[FZ(base + 64*j)];
        bfy8(zx, g_t1a[o], g_t1b[o], g_t1c[o]);
        #pragma unroll
        for (int j = 0; j < 8; j++) z[FZ(base + 64*j)] = zx[j];
    }
    __syncthreads();   // sync 3
    // ---- group 2: radix-8, S=64, q=8 (in-place per-thread; packed twiddles) ----
    {
        int o = tid & 7, base = (tid >> 3) * 64 + o;
        #pragma unroll
        for (int j = 0; j < 8; j++) zx[j] = z[FZ(base + 8*j)];
        bfy8(zx, g_t2a[o], g_t2b[o], g_t2c[o]);
        #pragma unroll
        for (int j = 0; j < 8; j++) z[FZ(base + 8*j)] = zx[j];
    }
    __syncthreads();   // sync 4
    // ---- group 3: radix-8, S=8, q=1 (unit twiddles), fused de-reversal ----
    {
        int base = tid * 8;
        const float2 one = make_float2(1.f, 0.f);
        #pragma unroll
        for (int j = 0; j < 8; j++) zx[j] = z[FZ(base + j)];
        bfy8(zx, one, one, one);
        #pragma unroll
        for (int j = 0; j < 8; j++) {
            int k = __brev((unsigned)(base + j)) >> 21;   // natural bin
            ys[YA(k)] = zx[j];
        }
    }
    __syncthreads();   // sync 5: ys = natural spectrum

    // ---- unpack amplitudes via conjugate-pair symmetry, packed candidates ----
    u64 pk[9];
    float Ssum = 0.f, Smax = 0.f;
    #pragma unroll
    for (int c = 0; c < 4; ++c) {
        int k = 1 + tid + 256*c;          // 1..1024
        int m = 2048 - k;                 // 1024..2047
        float2 Zk = ys[YA(k)];
        float2 Zm = ys[YA(m)];
        float er  = 0.5f * (Zk.x + Zm.x);
        float ei  = 0.5f * (Zk.y - Zm.y);
        float orr = 0.5f * (Zk.y + Zm.y);
        float oi  = -0.5f * (Zk.x - Zm.x);
        float2 w = g_rot[k];
        float pr = w.x*orr - w.y*oi;
        float pi = w.x*oi  + w.y*orr;
        float xr = er + pr, xi2 = ei + pi;
        float ampk = sqrtf(xr*xr + xi2*xi2);
        float qr = er - pr, qi = ei - pi;
        float ampm = sqrtf(qr*qr + qi*qi);
        pk[c] = packcand(ampk, k);
        Ssum += ampk; Smax = fmaxf(Smax, ampk);
        if (k == 1024) { pk[4+c] = 0ull; }   // self-pair duplicate
        else {
            pk[4+c] = packcand(ampm, m);
            Ssum += ampm; Smax = fmaxf(Smax, ampm);
        }
    }
    pk[8] = 0ull;

    u64 c0 = 0ull, cN = 0ull;
    if (tid == 0) {
        float2 Z0 = ys[0];                // YA(0)==0
        float a0 = fabsf(Z0.x + Z0.y);    // bin 0
        float aN = fabsf(Z0.x - Z0.y);    // bin 2048
        c0 = packcand(a0, 0); cN = packcand(aN, 2048);
        Ssum += a0 + aN;
        Smax = fmaxf(Smax, fmaxf(a0, aN));
    }

    // sort pk[0..7] descending (packed order = value desc, key asc), Batcher
    #define CE(i,j) { if (pk[i] < pk[j]) { u64 t=pk[i]; pk[i]=pk[j]; pk[j]=t; } }
    CE(0,1) CE(2,3) CE(4,5) CE(6,7)
    CE(0,2) CE(1,3) CE(4,6) CE(5,7)
    CE(1,2) CE(5,6)
    CE(0,4) CE(1,5) CE(2,6) CE(3,7)
    CE(2,4) CE(3,5)
    CE(1,2) CE(3,4) CE(5,6)
    // tid0: insert bins 0 and 2048 (insert-with-drop keeps thread top-9)
    if (tid == 0) {
        if (c0 > pk[8]) pk[8] = c0;
        CE(7,8) CE(6,7) CE(5,6) CE(4,5) CE(3,4) CE(2,3) CE(1,2) CE(0,1)
        if (cN > pk[8]) pk[8] = cN;
        CE(7,8) CE(6,7) CE(5,6) CE(4,5) CE(3,4) CE(2,3) CE(1,2) CE(0,1)
    } else {
        CE(7,8) CE(6,7) CE(5,6) CE(4,5) CE(3,4) CE(2,3) CE(1,2) CE(0,1)
    }
    #undef CE

    // amp sum/max warp partials
    {
        float sv = Ssum, mv = Smax;
        #pragma unroll
        for (int o = 16; o > 0; o >>= 1) {
            sv += __shfl_down_sync(~0u, sv, o);
            mv = fmaxf(mv, __shfl_down_sync(~0u, mv, o));
        }
        if (lane == 0) { red[72 + warp] = sv; red[80 + warp] = mv; }
    }

    // ---- Phase A: warp-local tournament, register shift-queue (no smem lists) ----
    {
        #pragma unroll
        for (int r = 0; r < 9; ++r) {
            u64 h = pk[0];
            u64 b = h;
            #pragma unroll
            for (int o = 16; o > 0; o >>= 1) {
                u64 ob = __shfl_xor_sync(~0u, b, o);
                if (ob > b) b = ob;
            }
            if (h == b && h != 0ull) {      // this lane's head won: pop it
                #pragma unroll
                for (int qq = 0; qq < 8; qq++) pk[qq] = pk[qq+1];
                pk[8] = 0ull;
            }
            if (lane == 0) wl[warp*9 + r] = b;
        }
    }
    __syncthreads();   // sync 6: warp winners + amp partials visible

    // ---- Phase B: warp 0 merges 8 warp lists (register shift-queue) ----
    if (warp == 0) {
        u64 q[9];
        #pragma unroll
        for (int r = 0; r < 9; ++r) q[r] = (lane < 8) ? wl[lane*9 + r] : 0ull;
        #pragma unroll
        for (int r = 0; r < 9; ++r) {
            u64 h = q[0];
            u64 b = h;
            #pragma unroll
            for (int o = 4; o > 0; o >>= 1) {
                u64 ob = __shfl_xor_sync(~0u, b, o);
                if (ob > b) b = ob;
            }
            if (h == b && h != 0ull) {
                #pragma unroll
                for (int qq = 0; qq < 8; qq++) q[qq] = q[qq+1];
                q[8] = 0ull;
            }
            if (lane == 0) wl[72 + r] = b;
        }
    }

    // ---- epilogue (thread 0, same warp as Phase B writes) ----
    if (tid == 0) {
        float s1 = 0.f, s2a = 0.f, s3 = 0.f, s4 = 0.f, R[5] = {0,0,0,0,0};
        float S = 0.f, maxamp = 0.f;
        #pragma unroll
        for (int i = 0; i < 8; i++) {
            s1 += red[0*8+i]; s2a += red[1*8+i]; s3 += red[2*8+i]; s4 += red[3*8+i];
            R[0] += red[4*8+i]; R[1] += red[5*8+i]; R[2] += red[6*8+i];
            R[3] += red[7*8+i]; R[4] += red[8*8+i];
            S += red[72+i]; maxamp = fmaxf(maxamp, red[80+i]);
        }
        float topv[9]; int topi[9];
        #pragma unroll
        for (int r = 0; r < 9; ++r) {
            u64 w = wl[72 + r];
            topv[r] = __uint_as_float((unsigned)(w >> 32));
            topi[r] = 0x7fffffff ^ (int)(unsigned)w;
        }
        // edge prefix/suffix sums
        float H[25], T[25];
        H[0] = 0.f; T[0] = 0.f;
        #pragma unroll
        for (int k = 0; k < 24; k++) {
            H[k+1] = H[k] + red[232 + k];
            T[k+1] = T[k] + red[279 - k];
        }

        const float m  = s1 * (1.0f / L_);
        const float d2 = s2a - (float)L_ * m * m;
        const float d3 = s3 - 3.f*m*s2a + 2.f*(float)L_*m*m*m;
        const float d4 = s4 - 4.f*m*s3 + 6.f*m*m*s2a - 3.f*(float)L_*m*m*m*m;

        const float var  = d2 / (float)(L_ - 1);
        const float stdv = sqrtf(var);
        const float se   = stdv + 1e-8f;
        const float se2  = se * se;
        const float skew = (d3 / (float)L_) / (se * se2 + 1e-8f);
        const float kurt = (d4 / (float)L_) / (se2 * se2 + 1e-8f) - 3.0f;

        const float total = S / (float)FBINS + 1e-8f;
        float lvlsum[3] = { topv[0]+topv[1]+topv[2]+topv[3]+topv[4],
                            topv[5]+topv[6], topv[7] };
        float g[3]; float prefix = 0.f;
        #pragma unroll
        for (int l = 0; l < 3; l++) {
            float rr = ((S - prefix) / (float)FBINS) / total;
            float lr = 0.25f * (float)(l + 1);
            float o = b2v[0];
            #pragma unroll
            for (int j = 0; j < 8; j++) {
                float h = rr * w1[j] + lr * w1[8 + j] + b1v[j];
                h = 0.5f * h * (1.0f + erff(h * 0.70710678118654752f));
                o += h * w2[j];
            }
            g[l] = 1.0f / (1.0f + expf(-o));
            prefix += lvlsum[l];
        }
        const float r1 = g[0], r2 = g[0]*g[1], r3 = g[0]*g[1]*g[2];
        const float rf[9] = {1.f,1.f,1.f,1.f,1.f, r1, r1, r2, r3};
        float cv[9]; int ci[9];
        #pragma unroll
        for (int i = 0; i < 9; i++) { cv[i] = topv[i]*rf[i]; ci[i] = topi[i]; }
        for (int i = 1; i < 9; i++) {           // value desc, index asc on ties
            float v = cv[i]; int id = ci[i]; int j = i - 1;
            while (j >= 0 && (cv[j] < v || (cv[j] == v && ci[j] > id))) {
                cv[j+1] = cv[j]; ci[j+1] = ci[j]; j--;
            }
            cv[j+1] = v; ci[j+1] = id;
        }

        const float invden = 1.0f / (maxamp + 2e-8f);
        float* op = out + (size_t)blockIdx.x * 19;
        op[0] = m; op[1] = stdv; op[2] = skew; op[3] = kurt;
        #pragma unroll
        for (int i = 0; i < 5; i++) {
            op[4 + i] = (float)ci[i] * (1.0f / (float)L_);
            op[9 + i] = cv[i] * invden;
        }
        const int lags2[5] = {1, 3, 6, 12, 24};
        #pragma unroll
        for (int q = 0; q < 5; q++) {
            int l = lags2[q];
            float acsum = R[q] - m * ((s1 - T[l]) + (s1 - H[l])) + (float)(L_ - l) * m * m;
            op[14 + q] = (acsum / (float)(L_ - l)) / se2;
        }
    }
}

// ---------------------------------------------------------------------------
extern "C" void kernel_launch(void* const* d_in, const int* in_sizes, int n_in,
                              void* d_out, int out_size) {
    const float* x  = (const float*)d_in[0];
    const float* w1 = (const float*)d_in[1];
    const float* b1 = (const float*)d_in[2];
    const float* w2 = (const float*)d_in[3];
    const float* b2 = (const float*)d_in[4];
    float* out = (float*)d_out;

    dim3 tb(8, 32);
    dim3 tg(L_ / 32, N_ / 32, B_);
    transpose_kernel<<<tg, tb>>>(x);

    feat_kernel<<<NSERIES, NT>>>(w1, b1, w2, b2, out);
}

// round 16
// speedup vs baseline: 1.3447x; 1.1435x over previous
#include <cuda_runtime.h>
#include <math.h>

#define B_ 32
#define L_ 4096
#define N_ 256
#define NF 2048          // packed complex FFT size (L/2)
#define FBINS 2049       // rfft bins
#define NT 256
#define NSERIES (B_*N_)

typedef unsigned long long u64;

__device__ float  g_xt[(size_t)B_*N_*L_];   // (B,N,L) transposed input
__device__ float2 g_tw[NF/2];               // exp(-2*pi*i*j/2048)
__device__ float2 g_rot[NF];                // exp(-pi*i*k/2048)
// packed per-stage twiddle tables (consecutive / broadcast loads)
__device__ float2 g_t0b[512];               // tw(2i)
__device__ float2 g_t1a[64], g_t1b[64], g_t1c[64];   // tw(4o), tw(8o), tw(16o)
__device__ float2 g_t2a[8],  g_t2b[8],  g_t2c[8];    // tw(32o), tw(64o), tw(128o)

// XOR swizzle on float2 indices: conflict-free smem FFT exchanges
#define FZ(a) ((a) ^ (((a) >> 3) & 0xF))
// padded natural-order spectrum index
#define YA(k) ((k) + ((k) >> 3))
// float4-level XOR swizzle for the series buffer (phase-1 store / g0 read)
#define S4(a) ((a) ^ (((a) >> 3) & 7))

// packed candidate: value desc, key asc in ONE u64 compare (amps >= 0)
__device__ __forceinline__ u64 packcand(float v, int k) {
    return ((u64)__float_as_uint(v) << 32) | (unsigned)(0x7fffffff ^ k);
}

__device__ __forceinline__ float2 cmul(float2 a, float2 b) {
    return make_float2(a.x*b.x - a.y*b.y, a.x*b.y + a.y*b.x);
}
__device__ __forceinline__ float2 cadd(float2 a, float2 b) { return make_float2(a.x+b.x, a.y+b.y); }
__device__ __forceinline__ float2 csub(float2 a, float2 b) { return make_float2(a.x-b.x, a.y-b.y); }
__device__ __forceinline__ float2 cnegi(float2 a) { return make_float2(a.y, -a.x); }  // a * (-i)

// ---------------------------------------------------------------------------
// Vectorized tiled transpose x (B,L,N) -> g_xt (B,N,L).
// Block (8,32): LDG.128 along N, STG.128 along L; 33-pad tile.
// Block (0,0,0) also fills twiddle tables.
__global__ void transpose_kernel(const float* __restrict__ x) {
    __shared__ float tile[32][33];   // [l][n]
    int b  = blockIdx.z;
    int l0 = blockIdx.x << 5;
    int n0 = blockIdx.y << 5;
    int tx = threadIdx.x, ty = threadIdx.y;   // (8, 32)
    if (blockIdx.x == 0 && blockIdx.y == 0 && blockIdx.z == 0) {
        int tid = ty * 8 + tx;
        for (int i = tid; i < NF/2; i += 256) {
            float ang = -6.2831853071795864769f * (float)i / (float)NF;
            float sn, cs; sincosf(ang, &sn, &cs);
            g_tw[i] = make_float2(cs, sn);
        }
        for (int i = tid; i < NF; i += 256) {
            float ang = -3.1415926535897932385f * (float)i / (float)NF;
            float sn, cs; sincosf(ang, &sn, &cs);
            g_rot[i] = make_float2(cs, sn);
        }
        for (int i = tid; i < 512; i += 256) {
            float ang = -6.2831853071795864769f * (float)(2*i) / (float)NF;
            float sn, cs; sincosf(ang, &sn, &cs);
            g_t0b[i] = make_float2(cs, sn);
        }
        if (tid < 64) {
            float a1 = -6.2831853071795864769f * (float)(4*tid)  / (float)NF;
            float a2 = -6.2831853071795864769f * (float)(8*tid)  / (float)NF;
            float a3 = -6.2831853071795864769f * (float)(16*tid) / (float)NF;
            float sn, cs;
            sincosf(a1, &sn, &cs); g_t1a[tid] = make_float2(cs, sn);
            sincosf(a2, &sn, &cs); g_t1b[tid] = make_float2(cs, sn);
            sincosf(a3, &sn, &cs); g_t1c[tid] = make_float2(cs, sn);
        }
        if (tid < 8) {
            float a1 = -6.2831853071795864769f * (float)(32*tid)  / (float)NF;
            float a2 = -6.2831853071795864769f * (float)(64*tid)  / (float)NF;
            float a3 = -6.2831853071795864769f * (float)(128*tid) / (float)NF;
            float sn, cs;
            sincosf(a1, &sn, &cs); g_t2a[tid] = make_float2(cs, sn);
            sincosf(a2, &sn, &cs); g_t2b[tid] = make_float2(cs, sn);
            sincosf(a3, &sn, &cs); g_t2c[tid] = make_float2(cs, sn);
        }
    }
    {
        float4 v = *(const float4*)(x + ((size_t)b * L_ + (l0 + ty)) * N_ + n0 + 4*tx);
        tile[ty][4*tx + 0] = v.x;
        tile[ty][4*tx + 1] = v.y;
        tile[ty][4*tx + 2] = v.z;
        tile[ty][4*tx + 3] = v.w;
    }
    __syncthreads();
    {
        float4 v;
        v.x = tile[4*tx + 0][ty];
        v.y = tile[4*tx + 1][ty];
        v.z = tile[4*tx + 2][ty];
        v.w = tile[4*tx + 3][ty];
        *(float4*)(g_xt + ((size_t)b * N_ + (n0 + ty)) * L_ + l0 + 4*tx) = v;
    }
}

// ---------------------------------------------------------------------------
// radix-4 DIF butterfly (in-place digit placement)
__device__ __forceinline__ void bfy4(float2* x, float2 wa, float2 wb) {
    float2 wami = cnegi(wa);
    float2 t0 = cadd(x[0], x[2]), u0 = cmul(csub(x[0], x[2]), wa);
    float2 t1 = cadd(x[1], x[3]), u1 = cmul(csub(x[1], x[3]), wami);
    x[0] = cadd(t0, t1); x[1] = cmul(csub(t0, t1), wb);
    x[2] = cadd(u0, u1); x[3] = cmul(csub(u0, u1), wb);
}

// radix-8 DIF butterfly = 3 in-place radix-2 stages on 8 register values.
__device__ __forceinline__ void bfy8(float2* x, float2 wa, float2 wb, float2 wc) {
    const float R2 = 0.70710678118654752440f;
    float2 wa1 = cmul(wa, make_float2(R2, -R2));
    float2 wa2 = cnegi(wa);
    float2 wa3 = cnegi(wa1);
    float2 wbi = cnegi(wb);
    float2 d;
    d = csub(x[0], x[4]); x[0] = cadd(x[0], x[4]); x[4] = cmul(d, wa);
    d = csub(x[1], x[5]); x[1] = cadd(x[1], x[5]); x[5] = cmul(d, wa1);
    d = csub(x[2], x[6]); x[2] = cadd(x[2], x[6]); x[6] = cmul(d, wa2);
    d = csub(x[3], x[7]); x[3] = cadd(x[3], x[7]); x[7] = cmul(d, wa3);
    d = csub(x[0], x[2]); x[0] = cadd(x[0], x[2]); x[2] = cmul(d, wb);
    d = csub(x[1], x[3]); x[1] = cadd(x[1], x[3]); x[3] = cmul(d, wbi);
    d = csub(x[4], x[6]); x[4] = cadd(x[4], x[6]); x[6] = cmul(d, wb);
    d = csub(x[5], x[7]); x[5] = cadd(x[5], x[7]); x[7] = cmul(d, wbi);
    d = csub(x[0], x[1]); x[0] = cadd(x[0], x[1]); x[1] = cmul(d, wc);
    d = csub(x[2], x[3]); x[2] = cadd(x[2], x[3]); x[3] = cmul(d, wc);
    d = csub(x[4], x[5]); x[4] = cadd(x[4], x[5]); x[5] = cmul(d, wc);
    d = csub(x[6], x[7]); x[6] = cadd(x[6], x[7]); x[7] = cmul(d, wc);
}

// ---------------------------------------------------------------------------
// One CTA per (b,n) series.
__global__ __launch_bounds__(NT, 4) void feat_kernel(
    const float* __restrict__ w1, const float* __restrict__ b1v,
    const float* __restrict__ w2, const float* __restrict__ b2v,
    float* __restrict__ out)
{
    __shared__ __align__(16) float s[4608];  // series (S4-swizzled) / FFT z[] (FZ-swizzled)
    __shared__ float2 ys[2304];  // g0 ping-pong scratch; later natural-order spectrum (YA padding)
    __shared__ u64   wl[81];     // 8 warp top-9 lists + global top-9
    __shared__ float red[304];
    // red: [0..71] 9x8 moment partials | [72..79] ampsum | [80..87] ampmax
    //      [232..255] head24 | [256..279] tail24

    const int tid  = threadIdx.x;
    const int lane = tid & 31, warp = tid >> 5;
    const int lags[5] = {1, 3, 6, 12, 24};

    // ---- phase 1: contiguous load, S4-swizzled STS (conflict-free), raw moments ----
    float xl[16];
    {
        const float4* __restrict__ src4 =
            (const float4*)(g_xt + (size_t)blockIdx.x * L_ + tid * 16);
        float4* sm4 = (float4*)s;
        #pragma unroll
        for (int c = 0; c < 4; ++c) {
            float4 v = src4[c];
            sm4[S4(tid*4 + c)] = v;
            xl[4*c+0] = v.x; xl[4*c+1] = v.y; xl[4*c+2] = v.z; xl[4*c+3] = v.w;
        }
    }
    if (tid < 8) ((float4*)s)[1024 + tid] = make_float4(0.f, 0.f, 0.f, 0.f); // pad (S4 = identity here)

    // edge stashes (raw values) for autocorr boundary terms
    if (tid == 0) {
        for (int k = 0; k < 16; k++) red[232 + k] = xl[k];
    }
    if (tid == 1) {
        for (int k = 0; k < 8;  k++) red[248 + k] = xl[k];
    }
    if (tid == 254) {
        for (int k = 0; k < 8;  k++) red[256 + k] = xl[8 + k];
    }
    if (tid == 255) {
        for (int k = 0; k < 16; k++) red[264 + k] = xl[k];
    }

    float acc[9];   // s1 s2 s3 s4 R1 R3 R6 R12 R24 (raw sums)
    #pragma unroll
    for (int q = 0; q < 9; q++) acc[q] = 0.f;
    #pragma unroll
    for (int i = 0; i < 16; i++) {
        float v = xl[i], v2 = v*v;
        acc[0] += v; acc[1] += v2; acc[2] += v2*v; acc[3] += v2*v2;
        #pragma unroll
        for (int q = 0; q < 5; q++) {
            int j = i + lags[q];
            if (j < 16) acc[4+q] += v * xl[j];
        }
    }
    __syncthreads();   // sync 1: smem series complete (incl. zero pad)

    // cross-boundary lag products via warp shuffles (tail = next threads' xl);
    // lanes 30/31 fall back to smem (S4-swizzled; identical values, zero-pad at end)
    {
        const bool fixA = (lane == 31);   // shfl(+1) crosses warp
        const bool fixB = (lane >= 30);   // shfl(+2) crosses warp
        #pragma unroll
        for (int c2 = 0; c2 < 6; ++c2) {
            float tl4[4];
            #pragma unroll
            for (int kk = 0; kk < 4; kk++) {
                if (c2 < 4) tl4[kk] = __shfl_down_sync(~0u, xl[4*c2 + kk], 1);
                else        tl4[kk] = __shfl_down_sync(~0u, xl[4*(c2-4) + kk], 2);
            }
            if ((c2 < 4) ? fixA : fixB) {
                float4 v = ((const float4*)s)[S4(tid*4 + 4 + c2)];
                tl4[0] = v.x; tl4[1] = v.y; tl4[2] = v.z; tl4[3] = v.w;
            }
            #pragma unroll
            for (int q = 0; q < 5; q++) {
                int l = lags[q];
                #pragma unroll
                for (int kk = 0; kk < 4; kk++) {
                    int k = 4*c2 + kk;
                    int i = 16 + k - l;
                    if (k < l && i >= 0) acc[4+q] += xl[i] * tl4[kk];
                }
            }
        }
    }
    // warp-reduce 9 raw sums -> red partials
    #pragma unroll
    for (int q = 0; q < 9; q++) {
        float v = acc[q];
        #pragma unroll
        for (int o = 16; o > 0; o >>= 1) v += __shfl_down_sync(~0u, v, o);
        if (lane == 0) red[q*8 + warp] = v;
    }

    // ---- FFT group 0: radix-4 (S=2048), read s (S4 layout) -> write ys swizzled. ----
    float2* z = (float2*)s;
    const float2* s2 = (const float2*)s;
    float2 xa[4], xb[4];
    #pragma unroll
    for (int j = 0; j < 4; j++) {
        int va = tid + 512*j, vb = tid + 256 + 512*j;
        xa[j] = s2[(S4(va >> 1) << 1) | (va & 1)];
        xb[j] = s2[(S4(vb >> 1) << 1) | (vb & 1)];
    }
    bfy4(xa, g_tw[tid],       g_t0b[tid]);
    bfy4(xb, g_tw[tid + 256], g_t0b[tid + 256]);
    #pragma unroll
    for (int j = 0; j < 4; j++) {
        ys[FZ(tid + 512*j)]       = xa[j];
        ys[FZ(tid + 256 + 512*j)] = xb[j];
    }
    __syncthreads();   // sync 2: g0 output ready in ys

    float2 zx[8];
    // ---- group 1: radix-8, S=512, q=64 (reads ys, writes z; packed twiddles) ----
    {
        int o = tid & 63, base = (tid >> 6) * 512 + o;
        #pragma unroll
        for (int j = 0; j < 8; j++) zx[j] = ys[FZ(base + 64*j)];
        bfy8(zx, g_t1a[o], g_t1b[o], g_t1c[o]);
        #pragma unroll
        for (int j = 0; j < 8; j++) z[FZ(base + 64*j)] = zx[j];
    }
    __syncthreads();   // sync 3
    // ---- group 2: radix-8, S=64, q=8 (in-place per-thread; packed twiddles) ----
    {
        int o = tid & 7, base = (tid >> 3) * 64 + o;
        #pragma unroll
        for (int j = 0; j < 8; j++) zx[j] = z[FZ(base + 8*j)];
        bfy8(zx, g_t2a[o], g_t2b[o], g_t2c[o]);
        #pragma unroll
        for (int j = 0; j < 8; j++) z[FZ(base + 8*j)] = zx[j];
    }
    __syncthreads();   // sync 4
    // ---- group 3: radix-8, S=8, q=1 (unit twiddles), fused de-reversal ----
    {
        int base = tid * 8;
        const float2 one = make_float2(1.f, 0.f);
        #pragma unroll
        for (int j = 0; j < 8; j++) zx[j] = z[FZ(base + j)];
        bfy8(zx, one, one, one);
        #pragma unroll
        for (int j = 0; j < 8; j++) {
            int k = __brev((unsigned)(base + j)) >> 21;   // natural bin
            ys[YA(k)] = zx[j];
        }
    }
    __syncthreads();   // sync 5: ys = natural spectrum

    // ---- unpack amplitudes via conjugate-pair symmetry, packed candidates ----
    u64 pk[9];
    float Ssum = 0.f, Smax = 0.f;
    #pragma unroll
    for (int c = 0; c < 4; ++c) {
        int k = 1 + tid + 256*c;          // 1..1024
        int m = 2048 - k;                 // 1024..2047
        float2 Zk = ys[YA(k)];
        float2 Zm = ys[YA(m)];
        float er  = 0.5f * (Zk.x + Zm.x);
        float ei  = 0.5f * (Zk.y - Zm.y);
        float orr = 0.5f * (Zk.y + Zm.y);
        float oi  = -0.5f * (Zk.x - Zm.x);
        float2 w = g_rot[k];
        float pr = w.x*orr - w.y*oi;
        float pi = w.x*oi  + w.y*orr;
        float xr = er + pr, xi2 = ei + pi;
        float ampk = sqrtf(xr*xr + xi2*xi2);
        float qr = er - pr, qi = ei - pi;
        float ampm = sqrtf(qr*qr + qi*qi);
        pk[c] = packcand(ampk, k);
        Ssum += ampk; Smax = fmaxf(Smax, ampk);
        if (k == 1024) { pk[4+c] = 0ull; }   // self-pair duplicate
        else {
            pk[4+c] = packcand(ampm, m);
            Ssum += ampm; Smax = fmaxf(Smax, ampm);
        }
    }
    pk[8] = 0ull;

    u64 c0 = 0ull, cN = 0ull;
    if (tid == 0) {
        float2 Z0 = ys[0];                // YA(0)==0
        float a0 = fabsf(Z0.x + Z0.y);    // bin 0
        float aN = fabsf(Z0.x - Z0.y);    // bin 2048
        c0 = packcand(a0, 0); cN = packcand(aN, 2048);
        Ssum += a0 + aN;
        Smax = fmaxf(Smax, fmaxf(a0, aN));
    }

    // sort pk[0..7] descending (packed order = value desc, key asc), Batcher
    #define CE(i,j) { if (pk[i] < pk[j]) { u64 t=pk[i]; pk[i]=pk[j]; pk[j]=t; } }
    CE(0,1) CE(2,3) CE(4,5) CE(6,7)
    CE(0,2) CE(1,3) CE(4,6) CE(5,7)
    CE(1,2) CE(5,6)
    CE(0,4) CE(1,5) CE(2,6) CE(3,7)
    CE(2,4) CE(3,5)
    CE(1,2) CE(3,4) CE(5,6)
    // tid0: insert bins 0 and 2048 (insert-with-drop keeps thread top-9)
    if (tid == 0) {
        if (c0 > pk[8]) pk[8] = c0;
        CE(7,8) CE(6,7) CE(5,6) CE(4,5) CE(3,4) CE(2,3) CE(1,2) CE(0,1)
        if (cN > pk[8]) pk[8] = cN;
        CE(7,8) CE(6,7) CE(5,6) CE(4,5) CE(3,4) CE(2,3) CE(1,2) CE(0,1)
    } else {
        CE(7,8) CE(6,7) CE(5,6) CE(4,5) CE(3,4) CE(2,3) CE(1,2) CE(0,1)
    }
    #undef CE

    // amp sum/max warp partials
    {
        float sv = Ssum, mv = Smax;
        #pragma unroll
        for (int o = 16; o > 0; o >>= 1) {
            sv += __shfl_down_sync(~0u, sv, o);
            mv = fmaxf(mv, __shfl_down_sync(~0u, mv, o));
        }
        if (lane == 0) { red[72 + warp] = sv; red[80 + warp] = mv; }
    }

    // ---- Phase A: warp-local tournament, register shift-queue (no smem lists) ----
    {
        #pragma unroll
        for (int r = 0; r < 9; ++r) {
            u64 h = pk[0];
            u64 b = h;
            #pragma unroll
            for (int o = 16; o > 0; o >>= 1) {
                u64 ob = __shfl_xor_sync(~0u, b, o);
                if (ob > b) b = ob;
            }
            if (h == b && h != 0ull) {      // this lane's head won: pop it
                #pragma unroll
                for (int qq = 0; qq < 8; qq++) pk[qq] = pk[qq+1];
                pk[8] = 0ull;
            }
            if (lane == 0) wl[warp*9 + r] = b;
        }
    }
    __syncthreads();   // sync 6: warp winners + amp partials visible

    if (warp == 0) {
        // ---- Phase B: warp 0 merges 8 warp lists (register shift-queue) ----
        {
            u64 q[9];
            #pragma unroll
            for (int r = 0; r < 9; ++r) q[r] = (lane < 8) ? wl[lane*9 + r] : 0ull;
            #pragma unroll
            for (int r = 0; r < 9; ++r) {
                u64 h = q[0];
                u64 b = h;
                #pragma unroll
                for (int o = 4; o > 0; o >>= 1) {
                    u64 ob = __shfl_xor_sync(~0u, b, o);
                    if (ob > b) b = ob;
                }
                if (h == b && h != 0ull) {
                    #pragma unroll
                    for (int qq = 0; qq < 8; qq++) q[qq] = q[qq+1];
                    q[8] = 0ull;
                }
                if (lane == 0) wl[72 + r] = b;
            }
        }
        __syncwarp();   // lane 0's wl[72..] writes visible warp-wide

        // ---- lane-parallel epilogue ----
        // all lanes: global top-9 (broadcast smem reads)
        float topv[9]; int topi[9];
        #pragma unroll
        for (int r = 0; r < 9; ++r) {
            u64 w = wl[72 + r];
            topv[r] = __uint_as_float((unsigned)(w >> 32));
            topi[r] = 0x7fffffff ^ (int)(unsigned)w;
        }
        // partial reductions: lanes 0-8 moment groups, lane 9 ampsum, lane 10 ampmax
        float psum = 0.f;
        if (lane < 9) {
            #pragma unroll
            for (int i = 0; i < 8; i++) psum += red[lane*8 + i];
        } else if (lane == 9) {
            #pragma unroll
            for (int i = 0; i < 8; i++) psum += red[72 + i];
        } else if (lane == 10) {
            float mv = red[80];
            #pragma unroll
            for (int i = 1; i < 8; i++) mv = fmaxf(mv, red[80 + i]);
            psum = mv;
        }
        const float s1     = __shfl_sync(~0u, psum, 0);
        const float s2a    = __shfl_sync(~0u, psum, 1);
        const float s3     = __shfl_sync(~0u, psum, 2);
        const float s4     = __shfl_sync(~0u, psum, 3);
        const float S      = __shfl_sync(~0u, psum, 9);
        const float maxamp = __shfl_sync(~0u, psum, 10);
        const float Rq     = __shfl_sync(~0u, psum, 4 + (lane < 5 ? lane : 0));

        // shared scalar stats (all lanes; cheap)
        const float m  = s1 * (1.0f / L_);
        const float d2 = s2a - (float)L_ * m * m;
        const float var  = d2 / (float)(L_ - 1);
        const float stdv = sqrtf(var);
        const float se   = stdv + 1e-8f;
        const float se2  = se * se;

        // gates: lanes 0-23 evaluate one (level, hidden unit) each
        const float total = S / (float)FBINS + 1e-8f;
        const float lvl0 = topv[0]+topv[1]+topv[2]+topv[3]+topv[4];
        const float lvl1 = topv[5]+topv[6];
        const int gl = lane >> 3, gj = lane & 7;
        float opart = 0.f;
        if (lane < 24) {
            float prefix = (gl >= 1 ? lvl0 : 0.f) + (gl >= 2 ? lvl1 : 0.f);
            float rr = ((S - prefix) / (float)FBINS) / total;
            float lr = 0.25f * (float)(gl + 1);
            float h = rr * w1[gj] + lr * w1[8 + gj] + b1v[gj];
            h = 0.5f * h * (1.0f + erff(h * 0.70710678118654752f));
            opart = h * w2[gj];
        }
        opart += __shfl_down_sync(~0u, opart, 4);
        opart += __shfl_down_sync(~0u, opart, 2);
        opart += __shfl_down_sync(~0u, opart, 1);
        float osum = __shfl_sync(~0u, opart, 8 * (lane < 3 ? lane : 0));
        float sig = 0.f;
        if (lane < 3) sig = 1.0f / (1.0f + expf(-(osum + b2v[0])));
        const float g0 = __shfl_sync(~0u, sig, 0);
        const float g1 = __shfl_sync(~0u, sig, 1);
        const float g2 = __shfl_sync(~0u, sig, 2);

        float* op = out + (size_t)blockIdx.x * 19;

        // autocorr outputs: lanes 0-4 (one lag each; same summation order)
        if (lane < 5) {
            int l = lags[lane];
            float Hs = 0.f, Ts = 0.f;
            for (int k = 0; k < l; k++) { Hs += red[232 + k]; Ts += red[279 - k]; }
            float acsum = Rq - m * ((s1 - Ts) + (s1 - Hs)) + (float)(L_ - l) * m * m;
            op[14 + lane] = (acsum / (float)(L_ - l)) / se2;
        }

        // lane 0: scalar moments + top-5 decode
        if (lane == 0) {
            const float d3 = s3 - 3.f*m*s2a + 2.f*(float)L_*m*m*m;
            const float d4 = s4 - 4.f*m*s3 + 6.f*m*m*s2a - 3.f*(float)L_*m*m*m*m;
            const float skew = (d3 / (float)L_) / (se * se2 + 1e-8f);
            const float kurt = (d4 / (float)L_) / (se2 * se2 + 1e-8f) - 3.0f;

            const float r1 = g0, r2 = g0*g1, r3 = g0*g1*g2;
            const float rf[9] = {1.f,1.f,1.f,1.f,1.f, r1, r1, r2, r3};
            float cv[9]; int ci[9];
            #pragma unroll
            for (int i = 0; i < 9; i++) { cv[i] = topv[i]*rf[i]; ci[i] = topi[i]; }
            for (int i = 1; i < 9; i++) {           // value desc, index asc on ties
                float v = cv[i]; int id = ci[i]; int j = i - 1;
                while (j >= 0 && (cv[j] < v || (cv[j] == v && ci[j] > id))) {
                    cv[j+1] = cv[j]; ci[j+1] = ci[j]; j--;
                }
                cv[j+1] = v; ci[j+1] = id;
            }

            const float invden = 1.0f / (maxamp + 2e-8f);
            op[0] = m; op[1] = stdv; op[2] = skew; op[3] = kurt;
            #pragma unroll
            for (int i = 0; i < 5; i++) {
                op[4 + i] = (float)ci[i] * (1.0f / (float)L_);
                op[9 + i] = cv[i] * invden;
            }
        }
    }
}

// ---------------------------------------------------------------------------
extern "C" void kernel_launch(void* const* d_in, const int* in_sizes, int n_in,
                              void* d_out, int out_size) {
    const float* x  = (const float*)d_in[0];
    const float* w1 = (const float*)d_in[1];
    const float* b1 = (const float*)d_in[2];
    const float* w2 = (const float*)d_in[3];
    const float* b2 = (const float*)d_in[4];
    float* out = (float*)d_out;

    dim3 tb(8, 32);
    dim3 tg(L_ / 32, N_ / 32, B_);
    transpose_kernel<<<tg, tb>>>(x);

    feat_kernel<<<NSERIES, NT>>>(w1, b1, w2, b2, out);
}

// round 17
// speedup vs baseline: 1.3847x; 1.0298x over previous
#include <cuda_runtime.h>
#include <math.h>

#define B_ 32
#define L_ 4096
#define N_ 256
#define NF 2048          // packed complex FFT size (L/2)
#define FBINS 2049       // rfft bins
#define NT 256
#define NSERIES (B_*N_)

typedef unsigned long long u64;

__device__ float  g_xt[(size_t)B_*N_*L_];   // (B,N,L) transposed input
__device__ float2 g_tw[NF/2];               // exp(-2*pi*i*j/2048)
__device__ float2 g_rot[NF];                // exp(-pi*i*k/2048)
// packed per-stage twiddle tables (consecutive / broadcast loads)
__device__ float2 g_t0b[512];               // tw(2i)
__device__ float2 g_t1a[64], g_t1b[64], g_t1c[64];   // tw(4o), tw(8o), tw(16o)
__device__ float2 g_t2a[8],  g_t2b[8],  g_t2c[8];    // tw(32o), tw(64o), tw(128o)

// XOR swizzle on float2 indices: conflict-free smem FFT exchanges
#define FZ(a) ((a) ^ (((a) >> 3) & 0xF))
// padded natural-order spectrum index
#define YA(k) ((k) + ((k) >> 3))
// float4-level XOR swizzle for the series buffer (phase-1 store / g0 read)
#define S4(a) ((a) ^ (((a) >> 3) & 7))

// packed candidate: value desc, key asc in ONE u64 compare (amps >= 0)
__device__ __forceinline__ u64 packcand(float v, int k) {
    return ((u64)__float_as_uint(v) << 32) | (unsigned)(0x7fffffff ^ k);
}

__device__ __forceinline__ float2 cmul(float2 a, float2 b) {
    return make_float2(a.x*b.x - a.y*b.y, a.x*b.y + a.y*b.x);
}
__device__ __forceinline__ float2 cadd(float2 a, float2 b) { return make_float2(a.x+b.x, a.y+b.y); }
__device__ __forceinline__ float2 csub(float2 a, float2 b) { return make_float2(a.x-b.x, a.y-b.y); }
__device__ __forceinline__ float2 cnegi(float2 a) { return make_float2(a.y, -a.x); }  // a * (-i)

// ---------------------------------------------------------------------------
// Vectorized tiled transpose x (B,L,N) -> g_xt (B,N,L).
// 64(L)x32(N) tiles, block (8,32): 2 float4 loads + 2 float4 stores per thread.
// Block (0,0,0) also fills twiddle tables.
__global__ void transpose_kernel(const float* __restrict__ x) {
    __shared__ float tile[64][33];   // [l][n]
    int b  = blockIdx.z;
    int l0 = blockIdx.x << 6;
    int n0 = blockIdx.y << 5;
    int tx = threadIdx.x, ty = threadIdx.y;   // (8, 32)
    if (blockIdx.x == 0 && blockIdx.y == 0 && blockIdx.z == 0) {
        int tid = ty * 8 + tx;
        for (int i = tid; i < NF/2; i += 256) {
            float ang = -6.2831853071795864769f * (float)i / (float)NF;
            float sn, cs; sincosf(ang, &sn, &cs);
            g_tw[i] = make_float2(cs, sn);
        }
        for (int i = tid; i < NF; i += 256) {
            float ang = -3.1415926535897932385f * (float)i / (float)NF;
            float sn, cs; sincosf(ang, &sn, &cs);
            g_rot[i] = make_float2(cs, sn);
        }
        for (int i = tid; i < 512; i += 256) {
            float ang = -6.2831853071795864769f * (float)(2*i) / (float)NF;
            float sn, cs; sincosf(ang, &sn, &cs);
            g_t0b[i] = make_float2(cs, sn);
        }
        if (tid < 64) {
            float a1 = -6.2831853071795864769f * (float)(4*tid)  / (float)NF;
            float a2 = -6.2831853071795864769f * (float)(8*tid)  / (float)NF;
            float a3 = -6.2831853071795864769f * (float)(16*tid) / (float)NF;
            float sn, cs;
            sincosf(a1, &sn, &cs); g_t1a[tid] = make_float2(cs, sn);
            sincosf(a2, &sn, &cs); g_t1b[tid] = make_float2(cs, sn);
            sincosf(a3, &sn, &cs); g_t1c[tid] = make_float2(cs, sn);
        }
        if (tid < 8) {
            float a1 = -6.2831853071795864769f * (float)(32*tid)  / (float)NF;
            float a2 = -6.2831853071795864769f * (float)(64*tid)  / (float)NF;
            float a3 = -6.2831853071795864769f * (float)(128*tid) / (float)NF;
            float sn, cs;
            sincosf(a1, &sn, &cs); g_t2a[tid] = make_float2(cs, sn);
            sincosf(a2, &sn, &cs); g_t2b[tid] = make_float2(cs, sn);
            sincosf(a3, &sn, &cs); g_t2c[tid] = make_float2(cs, sn);
        }
    }
    // load: two float4 along N per thread (rows ty and ty+32)
    {
        float4 v0 = *(const float4*)(x + ((size_t)b * L_ + (l0 + ty)) * N_ + n0 + 4*tx);
        float4 v1 = *(const float4*)(x + ((size_t)b * L_ + (l0 + ty + 32)) * N_ + n0 + 4*tx);
        tile[ty][4*tx + 0] = v0.x; tile[ty][4*tx + 1] = v0.y;
        tile[ty][4*tx + 2] = v0.z; tile[ty][4*tx + 3] = v0.w;
        tile[ty + 32][4*tx + 0] = v1.x; tile[ty + 32][4*tx + 1] = v1.y;
        tile[ty + 32][4*tx + 2] = v1.z; tile[ty + 32][4*tx + 3] = v1.w;
    }
    __syncthreads();
    // store: two float4 along L per thread (cols 4tx and 4tx+32)
    {
        float4 v0, v1;
        v0.x = tile[4*tx + 0][ty]; v0.y = tile[4*tx + 1][ty];
        v0.z = tile[4*tx + 2][ty]; v0.w = tile[4*tx + 3][ty];
        v1.x = tile[4*tx + 32][ty]; v1.y = tile[4*tx + 33][ty];
        v1.z = tile[4*tx + 34][ty]; v1.w = tile[4*tx + 35][ty];
        float* dst = g_xt + ((size_t)b * N_ + (n0 + ty)) * L_ + l0 + 4*tx;
        *(float4*)dst        = v0;
        *(float4*)(dst + 32) = v1;
    }
}

// ---------------------------------------------------------------------------
// radix-4 DIF butterfly (in-place digit placement)
__device__ __forceinline__ void bfy4(float2* x, float2 wa, float2 wb) {
    float2 wami = cnegi(wa);
    float2 t0 = cadd(x[0], x[2]), u0 = cmul(csub(x[0], x[2]), wa);
    float2 t1 = cadd(x[1], x[3]), u1 = cmul(csub(x[1], x[3]), wami);
    x[0] = cadd(t0, t1); x[1] = cmul(csub(t0, t1), wb);
    x[2] = cadd(u0, u1); x[3] = cmul(csub(u0, u1), wb);
}

// radix-8 DIF butterfly = 3 in-place radix-2 stages on 8 register values.
__device__ __forceinline__ void bfy8(float2* x, float2 wa, float2 wb, float2 wc) {
    const float R2 = 0.70710678118654752440f;
    float2 wa1 = cmul(wa, make_float2(R2, -R2));
    float2 wa2 = cnegi(wa);
    float2 wa3 = cnegi(wa1);
    float2 wbi = cnegi(wb);
    float2 d;
    d = csub(x[0], x[4]); x[0] = cadd(x[0], x[4]); x[4] = cmul(d, wa);
    d = csub(x[1], x[5]); x[1] = cadd(x[1], x[5]); x[5] = cmul(d, wa1);
    d = csub(x[2], x[6]); x[2] = cadd(x[2], x[6]); x[6] = cmul(d, wa2);
    d = csub(x[3], x[7]); x[3] = cadd(x[3], x[7]); x[7] = cmul(d, wa3);
    d = csub(x[0], x[2]); x[0] = cadd(x[0], x[2]); x[2] = cmul(d, wb);
    d = csub(x[1], x[3]); x[1] = cadd(x[1], x[3]); x[3] = cmul(d, wbi);
    d = csub(x[4], x[6]); x[4] = cadd(x[4], x[6]); x[6] = cmul(d, wb);
    d = csub(x[5], x[7]); x[5] = cadd(x[5], x[7]); x[7] = cmul(d, wbi);
    d = csub(x[0], x[1]); x[0] = cadd(x[0], x[1]); x[1] = cmul(d, wc);
    d = csub(x[2], x[3]); x[2] = cadd(x[2], x[3]); x[3] = cmul(d, wc);
    d = csub(x[4], x[5]); x[4] = cadd(x[4], x[5]); x[5] = cmul(d, wc);
    d = csub(x[6], x[7]); x[6] = cadd(x[6], x[7]); x[7] = cmul(d, wc);
}

// ---------------------------------------------------------------------------
// One CTA per (b,n) series.
__global__ __launch_bounds__(NT, 4) void feat_kernel(
    const float* __restrict__ w1, const float* __restrict__ b1v,
    const float* __restrict__ w2, const float* __restrict__ b2v,
    float* __restrict__ out)
{
    __shared__ __align__(16) float s[4608];  // series (S4-swizzled) / FFT z[] (FZ-swizzled)
    __shared__ float2 ys[2304];  // g0 ping-pong scratch; later natural-order spectrum (YA padding)
    __shared__ u64   wl[81];     // 8 warp top-9 lists + global top-9
    __shared__ float red[304];
    // red: [0..71] 9x8 moment partials | [72..79] ampsum | [80..87] ampmax
    //      [232..255] head24 | [256..279] tail24

    const int tid  = threadIdx.x;
    const int lane = tid & 31, warp = tid >> 5;
    const int lags[5] = {1, 3, 6, 12, 24};

    // ---- phase 1: contiguous load, S4-swizzled STS (conflict-free), raw moments ----
    float xl[16];
    {
        const float4* __restrict__ src4 =
            (const float4*)(g_xt + (size_t)blockIdx.x * L_ + tid * 16);
        float4* sm4 = (float4*)s;
        #pragma unroll
        for (int c = 0; c < 4; ++c) {
            float4 v = src4[c];
            sm4[S4(tid*4 + c)] = v;
            xl[4*c+0] = v.x; xl[4*c+1] = v.y; xl[4*c+2] = v.z; xl[4*c+3] = v.w;
        }
    }
    if (tid < 8) ((float4*)s)[1024 + tid] = make_float4(0.f, 0.f, 0.f, 0.f); // pad (S4 = identity here)

    // edge stashes (raw values) for autocorr boundary terms
    if (tid == 0) {
        for (int k = 0; k < 16; k++) red[232 + k] = xl[k];
    }
    if (tid == 1) {
        for (int k = 0; k < 8;  k++) red[248 + k] = xl[k];
    }
    if (tid == 254) {
        for (int k = 0; k < 8;  k++) red[256 + k] = xl[8 + k];
    }
    if (tid == 255) {
        for (int k = 0; k < 16; k++) red[264 + k] = xl[k];
    }

    float acc[9];   // s1 s2 s3 s4 R1 R3 R6 R12 R24 (raw sums)
    #pragma unroll
    for (int q = 0; q < 9; q++) acc[q] = 0.f;
    #pragma unroll
    for (int i = 0; i < 16; i++) {
        float v = xl[i], v2 = v*v;
        acc[0] += v; acc[1] += v2; acc[2] += v2*v; acc[3] += v2*v2;
        #pragma unroll
        for (int q = 0; q < 5; q++) {
            int j = i + lags[q];
            if (j < 16) acc[4+q] += v * xl[j];
        }
    }
    __syncthreads();   // sync 1: smem series complete (incl. zero pad)

    // cross-boundary lag products via warp shuffles (tail = next threads' xl);
    // lanes 30/31 fall back to smem (S4-swizzled; identical values, zero-pad at end)
    {
        const bool fixA = (lane == 31);   // shfl(+1) crosses warp
        const bool fixB = (lane >= 30);   // shfl(+2) crosses warp
        #pragma unroll
        for (int c2 = 0; c2 < 6; ++c2) {
            float tl4[4];
            #pragma unroll
            for (int kk = 0; kk < 4; kk++) {
                if (c2 < 4) tl4[kk] = __shfl_down_sync(~0u, xl[4*c2 + kk], 1);
                else        tl4[kk] = __shfl_down_sync(~0u, xl[4*(c2-4) + kk], 2);
            }
            if ((c2 < 4) ? fixA : fixB) {
                float4 v = ((const float4*)s)[S4(tid*4 + 4 + c2)];
                tl4[0] = v.x; tl4[1] = v.y; tl4[2] = v.z; tl4[3] = v.w;
            }
            #pragma unroll
            for (int q = 0; q < 5; q++) {
                int l = lags[q];
                #pragma unroll
                for (int kk = 0; kk < 4; kk++) {
                    int k = 4*c2 + kk;
                    int i = 16 + k - l;
                    if (k < l && i >= 0) acc[4+q] += xl[i] * tl4[kk];
                }
            }
        }
    }
    // warp-reduce 9 raw sums -> red partials
    #pragma unroll
    for (int q = 0; q < 9; q++) {
        float v = acc[q];
        #pragma unroll
        for (int o = 16; o > 0; o >>= 1) v += __shfl_down_sync(~0u, v, o);
        if (lane == 0) red[q*8 + warp] = v;
    }

    // ---- FFT group 0: radix-4 (S=2048), read s (S4 layout) -> write ys swizzled. ----
    float2* z = (float2*)s;
    const float2* s2 = (const float2*)s;
    float2 xa[4], xb[4];
    #pragma unroll
    for (int j = 0; j < 4; j++) {
        int va = tid + 512*j, vb = tid + 256 + 512*j;
        xa[j] = s2[(S4(va >> 1) << 1) | (va & 1)];
        xb[j] = s2[(S4(vb >> 1) << 1) | (vb & 1)];
    }
    bfy4(xa, g_tw[tid],       g_t0b[tid]);
    bfy4(xb, g_tw[tid + 256], g_t0b[tid + 256]);
    #pragma unroll
    for (int j = 0; j < 4; j++) {
        ys[FZ(tid + 512*j)]       = xa[j];
        ys[FZ(tid + 256 + 512*j)] = xb[j];
    }
    __syncthreads();   // sync 2: g0 output ready in ys

    float2 zx[8];
    // ---- group 1: radix-8, S=512, q=64 (reads ys, writes z; packed twiddles) ----
    {
        int o = tid & 63, base = (tid >> 6) * 512 + o;
        #pragma unroll
        for (int j = 0; j < 8; j++) zx[j] = ys[FZ(base + 64*j)];
        bfy8(zx, g_t1a[o], g_t1b[o], g_t1c[o]);
        #pragma unroll
        for (int j = 0; j < 8; j++) z[FZ(base + 64*j)] = zx[j];
    }
    __syncthreads();   // sync 3
    // ---- group 2: radix-8, S=64, q=8 (in-place per-thread; packed twiddles) ----
    {
        int o = tid & 7, base = (tid >> 3) * 64 + o;
        #pragma unroll
        for (int j = 0; j < 8; j++) zx[j] = z[FZ(base + 8*j)];
        bfy8(zx, g_t2a[o], g_t2b[o], g_t2c[o]);
        #pragma unroll
        for (int j = 0; j < 8; j++) z[FZ(base + 8*j)] = zx[j];
    }
    __syncthreads();   // sync 4
    // ---- group 3: radix-8, S=8, q=1 (unit twiddles), fused de-reversal ----
    {
        int base = tid * 8;
        const float2 one = make_float2(1.f, 0.f);
        #pragma unroll
        for (int j = 0; j < 8; j++) zx[j] = z[FZ(base + j)];
        bfy8(zx, one, one, one);
        #pragma unroll
        for (int j = 0; j < 8; j++) {
            int k = __brev((unsigned)(base + j)) >> 21;   // natural bin
            ys[YA(k)] = zx[j];
        }
    }
    __syncthreads();   // sync 5: ys = natural spectrum

    // ---- unpack amplitudes via conjugate-pair symmetry, packed candidates ----
    u64 pk[9];
    float Ssum = 0.f, Smax = 0.f;
    #pragma unroll
    for (int c = 0; c < 4; ++c) {
        int k = 1 + tid + 256*c;          // 1..1024
        int m = 2048 - k;                 // 1024..2047
        float2 Zk = ys[YA(k)];
        float2 Zm = ys[YA(m)];
        float er  = 0.5f * (Zk.x + Zm.x);
        float ei  = 0.5f * (Zk.y - Zm.y);
        float orr = 0.5f * (Zk.y + Zm.y);
        float oi  = -0.5f * (Zk.x - Zm.x);
        float2 w = g_rot[k];
        float pr = w.x*orr - w.y*oi;
        float pi = w.x*oi  + w.y*orr;
        float xr = er + pr, xi2 = ei + pi;
        float ampk = sqrtf(xr*xr + xi2*xi2);
        float qr = er - pr, qi = ei - pi;
        float ampm = sqrtf(qr*qr + qi*qi);
        pk[c] = packcand(ampk, k);
        Ssum += ampk; Smax = fmaxf(Smax, ampk);
        if (k == 1024) { pk[4+c] = 0ull; }   // self-pair duplicate
        else {
            pk[4+c] = packcand(ampm, m);
            Ssum += ampm; Smax = fmaxf(Smax, ampm);
        }
    }
    pk[8] = 0ull;

    u64 c0 = 0ull, cN = 0ull;
    if (tid == 0) {
        float2 Z0 = ys[0];                // YA(0)==0
        float a0 = fabsf(Z0.x + Z0.y);    // bin 0
        float aN = fabsf(Z0.x - Z0.y);    // bin 2048
        c0 = packcand(a0, 0); cN = packcand(aN, 2048);
        Ssum += a0 + aN;
        Smax = fmaxf(Smax, fmaxf(a0, aN));
    }

    // sort pk[0..7] descending (packed order = value desc, key asc), Batcher
    #define CE(i,j) { if (pk[i] < pk[j]) { u64 t=pk[i]; pk[i]=pk[j]; pk[j]=t; } }
    CE(0,1) CE(2,3) CE(4,5) CE(6,7)
    CE(0,2) CE(1,3) CE(4,6) CE(5,7)
    CE(1,2) CE(5,6)
    CE(0,4) CE(1,5) CE(2,6) CE(3,7)
    CE(2,4) CE(3,5)
    CE(1,2) CE(3,4) CE(5,6)
    // tid0: insert bins 0 and 2048 (insert-with-drop keeps thread top-9)
    if (tid == 0) {
        if (c0 > pk[8]) pk[8] = c0;
        CE(7,8) CE(6,7) CE(5,6) CE(4,5) CE(3,4) CE(2,3) CE(1,2) CE(0,1)
        if (cN > pk[8]) pk[8] = cN;
        CE(7,8) CE(6,7) CE(5,6) CE(4,5) CE(3,4) CE(2,3) CE(1,2) CE(0,1)
    } else {
        CE(7,8) CE(6,7) CE(5,6) CE(4,5) CE(3,4) CE(2,3) CE(1,2) CE(0,1)
    }
    #undef CE

    // amp sum/max warp partials
    {
        float sv = Ssum, mv = Smax;
        #pragma unroll
        for (int o = 16; o > 0; o >>= 1) {
            sv += __shfl_down_sync(~0u, sv, o);
            mv = fmaxf(mv, __shfl_down_sync(~0u, mv, o));
        }
        if (lane == 0) { red[72 + warp] = sv; red[80 + warp] = mv; }
    }

    // ---- Phase A: warp-local tournament, register shift-queue (no smem lists) ----
    {
        #pragma unroll
        for (int r = 0; r < 9; ++r) {
            u64 h = pk[0];
            u64 b = h;
            #pragma unroll
            for (int o = 16; o > 0; o >>= 1) {
                u64 ob = __shfl_xor_sync(~0u, b, o);
                if (ob > b) b = ob;
            }
            if (h == b && h != 0ull) {      // this lane's head won: pop it
                #pragma unroll
                for (int qq = 0; qq < 8; qq++) pk[qq] = pk[qq+1];
                pk[8] = 0ull;
            }
            if (lane == 0) wl[warp*9 + r] = b;
        }
    }
    __syncthreads();   // sync 6: warp winners + amp partials visible

    if (warp == 0) {
        // ---- Phase B: warp 0 merges 8 warp lists (register shift-queue) ----
        {
            u64 q[9];
            #pragma unroll
            for (int r = 0; r < 9; ++r) q[r] = (lane < 8) ? wl[lane*9 + r] : 0ull;
            #pragma unroll
            for (int r = 0; r < 9; ++r) {
                u64 h = q[0];
                u64 b = h;
                #pragma unroll
                for (int o = 4; o > 0; o >>= 1) {
                    u64 ob = __shfl_xor_sync(~0u, b, o);
                    if (ob > b) b = ob;
                }
                if (h == b && h != 0ull) {
                    #pragma unroll
                    for (int qq = 0; qq < 8; qq++) q[qq] = q[qq+1];
                    q[8] = 0ull;
                }
                if (lane == 0) wl[72 + r] = b;
            }
        }
        __syncwarp();   // lane 0's wl[72..] writes visible warp-wide

        // ---- lane-parallel epilogue ----
        float topv[9]; int topi[9];
        #pragma unroll
        for (int r = 0; r < 9; ++r) {
            u64 w = wl[72 + r];
            topv[r] = __uint_as_float((unsigned)(w >> 32));
            topi[r] = 0x7fffffff ^ (int)(unsigned)w;
        }
        // partial reductions: lanes 0-8 moment groups, lane 9 ampsum, lane 10 ampmax
        float psum = 0.f;
        if (lane < 9) {
            #pragma unroll
            for (int i = 0; i < 8; i++) psum += red[lane*8 + i];
        } else if (lane == 9) {
            #pragma unroll
            for (int i = 0; i < 8; i++) psum += red[72 + i];
        } else if (lane == 10) {
            float mv = red[80];
            #pragma unroll
            for (int i = 1; i < 8; i++) mv = fmaxf(mv, red[80 + i]);
            psum = mv;
        }
        const float s1     = __shfl_sync(~0u, psum, 0);
        const float s2a    = __shfl_sync(~0u, psum, 1);
        const float s3     = __shfl_sync(~0u, psum, 2);
        const float s4     = __shfl_sync(~0u, psum, 3);
        const float S      = __shfl_sync(~0u, psum, 9);
        const float maxamp = __shfl_sync(~0u, psum, 10);
        const float Rq     = __shfl_sync(~0u, psum, 4 + (lane < 5 ? lane : 0));

        // shared scalar stats (all lanes; cheap)
        const float m  = s1 * (1.0f / L_);
        const float d2 = s2a - (float)L_ * m * m;
        const float var  = d2 / (float)(L_ - 1);
        const float stdv = sqrtf(var);
        const float se   = stdv + 1e-8f;
        const float se2  = se * se;

        // gates: lanes 0-23 evaluate one (level, hidden unit) each
        const float total = S / (float)FBINS + 1e-8f;
        const float lvl0 = topv[0]+topv[1]+topv[2]+topv[3]+topv[4];
        const float lvl1 = topv[5]+topv[6];
        const int gl = lane >> 3, gj = lane & 7;
        float opart = 0.f;
        if (lane < 24) {
            float prefix = (gl >= 1 ? lvl0 : 0.f) + (gl >= 2 ? lvl1 : 0.f);
            float rr = ((S - prefix) / (float)FBINS) / total;
            float lr = 0.25f * (float)(gl + 1);
            float h = rr * w1[gj] + lr * w1[8 + gj] + b1v[gj];
            h = 0.5f * h * (1.0f + erff(h * 0.70710678118654752f));
            opart = h * w2[gj];
        }
        opart += __shfl_down_sync(~0u, opart, 4);
        opart += __shfl_down_sync(~0u, opart, 2);
        opart += __shfl_down_sync(~0u, opart, 1);
        float osum = __shfl_sync(~0u, opart, 8 * (lane < 3 ? lane : 0));
        float sig = 0.f;
        if (lane < 3) sig = 1.0f / (1.0f + expf(-(osum + b2v[0])));
        const float g0 = __shfl_sync(~0u, sig, 0);
        const float g1 = __shfl_sync(~0u, sig, 1);
        const float g2 = __shfl_sync(~0u, sig, 2);

        float* op = out + (size_t)blockIdx.x * 19;

        // autocorr outputs: lanes 0-4 (one lag each; same summation order)
        if (lane < 5) {
            int l = lags[lane];
            float Hs = 0.f, Ts = 0.f;
            for (int k = 0; k < l; k++) { Hs += red[232 + k]; Ts += red[279 - k]; }
            float acsum = Rq - m * ((s1 - Ts) + (s1 - Hs)) + (float)(L_ - l) * m * m;
            op[14 + lane] = (acsum / (float)(L_ - l)) / se2;
        }

        // lane 0: scalar moments + top-5 decode
        if (lane == 0) {
            const float d3 = s3 - 3.f*m*s2a + 2.f*(float)L_*m*m*m;
            const float d4 = s4 - 4.f*m*s3 + 6.f*m*m*s2a - 3.f*(float)L_*m*m*m*m;
            const float skew = (d3 / (float)L_) / (se * se2 + 1e-8f);
            const float kurt = (d4 / (float)L_) / (se2 * se2 + 1e-8f) - 3.0f;

            const float r1 = g0, r2 = g0*g1, r3 = g0*g1*g2;
            const float rf[9] = {1.f,1.f,1.f,1.f,1.f, r1, r1, r2, r3};
            float cv[9]; int ci[9];
            #pragma unroll
            for (int i = 0; i < 9; i++) { cv[i] = topv[i]*rf[i]; ci[i] = topi[i]; }
            for (int i = 1; i < 9; i++) {           // value desc, index asc on ties
                float v = cv[i]; int id = ci[i]; int j = i - 1;
                while (j >= 0 && (cv[j] < v || (cv[j] == v && ci[j] > id))) {
                    cv[j+1] = cv[j]; ci[j+1] = ci[j]; j--;
                }
                cv[j+1] = v; ci[j+1] = id;
            }

            const float invden = 1.0f / (maxamp + 2e-8f);
            op[0] = m; op[1] = stdv; op[2] = skew; op[3] = kurt;
            #pragma unroll
            for (int i = 0; i < 5; i++) {
                op[4 + i] = (float)ci[i] * (1.0f / (float)L_);
                op[9 + i] = cv[i] * invden;
            }
        }
    }
}

// ---------------------------------------------------------------------------
extern "C" void kernel_launch(void* const* d_in, const int* in_sizes, int n_in,
                              void* d_out, int out_size) {
    const float* x  = (const float*)d_in[0];
    const float* w1 = (const float*)d_in[1];
    const float* b1 = (const float*)d_in[2];
    const float* w2 = (const float*)d_in[3];
    const float* b2 = (const float*)d_in[4];
    float* out = (float*)d_out;

    dim3 tb(8, 32);
    dim3 tg(L_ / 64, N_ / 32, B_);
    transpose_kernel<<<tg, tb>>>(x);

    feat_kernel<<<NSERIES, NT>>>(w1, b1, w2, b2, out);
}